// round 3
// baseline (speedup 1.0000x reference)
#include <cuda_runtime.h>
#include <math.h>

#define Vv 34004
#define Ee 300
#define Hh 512
#define Bb 64
#define Tt 512
#define G4H 2048
#define BH (Bb * Hh)

typedef unsigned long long u64;

// packed fp32x2 FMA: d = a*b + c elementwise on (lo,hi) halves
__device__ __forceinline__ u64 fma2(u64 a, u64 b, u64 c) {
    u64 d;
    asm("fma.rn.f32x2 %0, %1, %2, %3;" : "=l"(d) : "l"(a), "l"(b), "l"(c));
    return d;
}
__device__ __forceinline__ float hsum2(u64 v) {
    float2 p = *(float2*)&v;
    return p.x + p.y;
}

// ---------------- scratch (device globals; no runtime allocation) ----------------
__device__ float g_xzf[67108864];      // [T][B][4H]  fw pre-activations
__device__ float g_xzb[67108864];      // [T][B][4H]  bw pre-activations (scan order)
__device__ float g_h[2 * 2 * BH];      // ping-pong: [buf][dir][B][H]
__device__ unsigned g_bar;             // grid barrier counter (monotonic per launch)

// =================================================================================
// Phase A: xz[t,b,:] = emb[tokens[b,t]] @ W + bias   (both directions)
// FP32 GEMM with packed FFMA2. M = B*T, N = 4096 (fw||bw), K = 300.
// BM=128, BN=64, BK=16, 256 threads, 8x4 micro-tile, double-buffered smem,
// k-pair packed smem layout for fma.rn.f32x2.
// =================================================================================
__global__ __launch_bounds__(256) void gemm_in(
    const int* __restrict__ tokens, const float* __restrict__ emb,
    const float* __restrict__ W_fw, const float* __restrict__ b_fw,
    const float* __restrict__ W_bw, const float* __restrict__ b_bw)
{
    // a2[buf][kk2][r][par]: pair (k=2*kk2, 2*kk2+1) for row r, contiguous
    __shared__ __align__(16) float a2[2][8 * 256];
    // w2[buf][kk2][n][par]
    __shared__ __align__(16) float w2[2][8 * 128];
    __shared__ int tok_s[128];

    const int tid = threadIdx.x;
    const int m0 = blockIdx.x * 128;
    const int nb = blockIdx.y;

    if (tid < 128) {
        int m = m0 + tid;
        int t = m >> 6, b = m & 63;
        tok_s[tid] = tokens[b * Tt + t];
    }

    const bool bw = (nb >= 32);
    const float* __restrict__ W    = bw ? W_bw : W_fw;
    const float* __restrict__ bias = bw ? b_bw : b_fw;
    const int n0 = (bw ? nb - 32 : nb) * 64;

    const int ry = tid >> 4;           // 0..15: rows ry*8..+8
    const int cx = tid & 15;           // 0..15: cols cx*4..+4

    // load-lane roles
    const int ar  = tid >> 1;          // emb row 0..127
    const int ak0 = (tid & 1) * 8;     // k sub-offset 0 or 8
    const int wk  = tid >> 4;          // W k-row 0..15
    const int wn  = (tid & 15) * 4;    // W col 0..60

    u64 acc2[8][4];
#pragma unroll
    for (int i = 0; i < 8; i++)
#pragma unroll
        for (int j = 0; j < 4; j++) acc2[i][j] = 0ull;

    __syncthreads();   // tok_s ready

    float4 areg0, areg1, wreg;
    const int NT = 19;  // ceil(300/16)

    // ---- smem store helpers (pair-packed) ----
    // A: thread covers k = ak0..ak0+7 of row ar -> 4 float2 pair-cells
    // W: thread covers k = wk, n = wn..wn+3 -> 4 scalar writes at parity wk&1
    auto store_a = [&](int buf) {
        float2* ad = (float2*)&a2[buf][0];          // float2 idx = kk2*128 + r
        int m2 = ak0 >> 1;                           // 0 or 4
        ad[(m2 + 0) * 128 + ar] = make_float2(areg0.x, areg0.y);
        ad[(m2 + 1) * 128 + ar] = make_float2(areg0.z, areg0.w);
        ad[(m2 + 2) * 128 + ar] = make_float2(areg1.x, areg1.y);
        ad[(m2 + 3) * 128 + ar] = make_float2(areg1.z, areg1.w);
    };
    auto store_w = [&](int buf) {
        int wk2 = wk >> 1, par = wk & 1;
        float* wd = &w2[buf][wk2 * 128 + par];
        wd[(wn + 0) * 2] = wreg.x;
        wd[(wn + 1) * 2] = wreg.y;
        wd[(wn + 2) * 2] = wreg.z;
        wd[(wn + 3) * 2] = wreg.w;
    };

    // prologue: global -> regs -> smem[0]
    {
        const float* src = emb + (size_t)tok_s[ar] * Ee + ak0;
        areg0 = *(const float4*)(src + 0);
        areg1 = *(const float4*)(src + 4);
        wreg  = *(const float4*)(W + (size_t)wk * G4H + n0 + wn);
        store_a(0);
        store_w(0);
    }
    __syncthreads();

    for (int kt = 0; kt < NT; kt++) {
        const int cur = kt & 1, nxt = cur ^ 1;

        // prefetch next tile into regs (overlaps FFMA2s below)
        if (kt + 1 < NT) {
            int k0 = (kt + 1) * 16;
            const float* src = emb + (size_t)tok_s[ar] * Ee + k0 + ak0;
            int ka = k0 + ak0;
            areg0 = (ka + 4 <= Ee) ? *(const float4*)(src + 0) : make_float4(0, 0, 0, 0);
            areg1 = (ka + 8 <= Ee) ? *(const float4*)(src + 4) : make_float4(0, 0, 0, 0);
            int kw = k0 + wk;
            wreg = (kw < Ee) ? *(const float4*)(W + (size_t)kw * G4H + n0 + wn)
                             : make_float4(0, 0, 0, 0);
        }

#pragma unroll
        for (int kk2 = 0; kk2 < 8; kk2++) {
            // 8 row-pairs for this thread: 16 consecutive floats
            const ulonglong2* arow =
                (const ulonglong2*)&a2[cur][kk2 * 256 + ry * 16];
            ulonglong2 av0 = arow[0], av1 = arow[1], av2 = arow[2], av3 = arow[3];
            const ulonglong2* wrow =
                (const ulonglong2*)&w2[cur][kk2 * 128 + cx * 8];
            ulonglong2 wv0 = wrow[0], wv1 = wrow[1];

            u64 ap[8] = {av0.x, av0.y, av1.x, av1.y, av2.x, av2.y, av3.x, av3.y};
            u64 wp[4] = {wv0.x, wv0.y, wv1.x, wv1.y};
#pragma unroll
            for (int i = 0; i < 8; i++)
#pragma unroll
                for (int j = 0; j < 4; j++)
                    acc2[i][j] = fma2(ap[i], wp[j], acc2[i][j]);
        }

        if (kt + 1 < NT) {
            store_a(nxt);
            store_w(nxt);
        }
        __syncthreads();
    }

    float4 bv = *(const float4*)(bias + n0 + cx * 4);
#pragma unroll
    for (int i = 0; i < 8; i++) {
        int m = m0 + ry * 8 + i;
        int t = m >> 6, b = m & 63;
        size_t row = bw ? ((size_t)(Tt - 1 - t) * Bb + b) : (size_t)m;
        float* dst = (bw ? g_xzb : g_xzf) + row * G4H + cx * 4 + n0;
        float4 o;
        o.x = hsum2(acc2[i][0]) + bv.x;
        o.y = hsum2(acc2[i][1]) + bv.y;
        o.z = hsum2(acc2[i][2]) + bv.z;
        o.w = hsum2(acc2[i][3]) + bv.w;
        *(float4*)dst = o;
    }
}

// =================================================================================
// init: reset barrier counter, seed h state buf0 from h0 inputs (every launch)
// =================================================================================
__global__ void init_kernel(const float* __restrict__ h0_fw,
                            const float* __restrict__ h0_bw)
{
    int i = blockIdx.x * blockDim.x + threadIdx.x;
    if (i == 0) g_bar = 0u;
    if (i < BH) {
        g_h[i]      = h0_fw[i];   // buf0, dir0
        g_h[BH + i] = h0_bw[i];   // buf0, dir1
    }
}

__device__ __forceinline__ float sigmoidf_fast(float x) {
    return __fdividef(1.f, 1.f + __expf(-x));
}

// =================================================================================
// Phase B: persistent bidirectional LSTM scan with FFMA2 inner product.
// 128 CTAs: dir = blk>>6, jblk = blk&63 -> 8 hidden units -> 32 z-columns.
// SMEM: U packed [256][64] (2k x 2c float4 cells), h stage [64][516],
//       z tile [32][66], c state [512]. Ping-pong h in L2, acquire-poll barrier.
// =================================================================================
#define HS 516
#define ZS 66
#define SCAN_SMEM_FLOATS (512 * 32 + 64 * HS + 32 * ZS + 512)
#define SCAN_SMEM_BYTES  (SCAN_SMEM_FLOATS * 4)

__global__ __launch_bounds__(256, 1) void lstm_scan(
    const float* __restrict__ U_fw, const float* __restrict__ U_bw,
    const float* __restrict__ c0_fw, const float* __restrict__ c0_bw,
    float* __restrict__ out, float* __restrict__ hT, float* __restrict__ cT)
{
    extern __shared__ __align__(16) float sm[];
    float* U_s = sm;                    // packed [k/2][32*2]: (2k x 2c) float4 cells
    float* h_s = U_s + 512 * 32;        // [64][HS]
    float* z_s = h_s + 64 * HS;         // [32][ZS] col-major [c][b]
    float* c_s = z_s + 32 * ZS;         // [512] (b*8 + jj)

    const int tid  = threadIdx.x;
    const int dir  = blockIdx.x >> 6;
    const int jblk = blockIdx.x & 63;
    const int j0   = jblk * 8;

    const float* __restrict__ U  = dir ? U_bw : U_fw;
    const float* __restrict__ c0 = dir ? c0_bw : c0_fw;
    const float* __restrict__ xz = dir ? g_xzb : g_xzf;

    // persistent U slice, packed: cell m covers k={2m,2m+1}:
    // float4 at (m*64 + c*2) = {U[2m][c],U[2m+1][c],U[2m][c+1],U[2m+1][c+1]}
    // -> as ulonglong2: .x = k-pair for col c, .y = k-pair for col c+1
    for (int i = tid; i < 512 * 32; i += 256) {
        int k = i >> 5, c = i & 31;
        U_s[(k >> 1) * 64 + c * 2 + (k & 1)] =
            U[(size_t)k * G4H + (c >> 3) * Hh + j0 + (c & 7)];
    }
    for (int i = tid; i < 512; i += 256)
        c_s[i] = c0[(i >> 3) * Hh + j0 + (i & 7)];

    const int ry  = tid >> 4;
    const int cx  = tid & 15;
    const int b0  = ry * 4;
    const int c0i = cx * 2;
    const int gate    = c0i >> 3;
    const int colbase = gate * Hh + j0 + (c0i & 7);

    for (int step = 0; step < Tt; step++) {
        const float* hbuf_r = g_h + (((step) & 1) * 2 + dir) * BH;
        float*       hbuf_w = g_h + (((step + 1) & 1) * 2 + dir) * BH;

        // issue xz DRAM loads FIRST (latency overlaps h staging)
        u64 acc2[4][2];
        {
            const float* row = xz + ((size_t)step * Bb + b0) * G4H + colbase;
#pragma unroll
            for (int i = 0; i < 4; i++) {
                float2 v = __ldcs((const float2*)(row + (size_t)i * G4H));
                float2 p0 = make_float2(v.x, 0.f);
                float2 p1 = make_float2(v.y, 0.f);
                acc2[i][0] = *(u64*)&p0;
                acc2[i][1] = *(u64*)&p1;
            }
        }

        // stage h from L2 (bypass L1 for cross-SM coherence)
        {
            const float4* hsrc = (const float4*)hbuf_r;
#pragma unroll 4
            for (int i = tid; i < BH / 4; i += 256) {
                float4 v = __ldcg(hsrc + i);
                int b = i >> 7;
                int k = (i & 127) * 4;
                *(float4*)&h_s[b * HS + k] = v;
            }
        }
        __syncthreads();

        // z += h @ U  (K=512): per 4-k: 6 LDS.128 + 16 FFMA2
#pragma unroll 4
        for (int k = 0; k < Hh; k += 4) {
            ulonglong2 h0 = *(const ulonglong2*)&h_s[(b0 + 0) * HS + k];
            ulonglong2 h1 = *(const ulonglong2*)&h_s[(b0 + 1) * HS + k];
            ulonglong2 h2 = *(const ulonglong2*)&h_s[(b0 + 2) * HS + k];
            ulonglong2 h3 = *(const ulonglong2*)&h_s[(b0 + 3) * HS + k];
            ulonglong2 ua = *(const ulonglong2*)&U_s[(k >> 1) * 64 + c0i * 2];
            ulonglong2 ub = *(const ulonglong2*)&U_s[((k >> 1) + 1) * 64 + c0i * 2];

            acc2[0][0] = fma2(h0.x, ua.x, acc2[0][0]);
            acc2[0][1] = fma2(h0.x, ua.y, acc2[0][1]);
            acc2[1][0] = fma2(h1.x, ua.x, acc2[1][0]);
            acc2[1][1] = fma2(h1.x, ua.y, acc2[1][1]);
            acc2[2][0] = fma2(h2.x, ua.x, acc2[2][0]);
            acc2[2][1] = fma2(h2.x, ua.y, acc2[2][1]);
            acc2[3][0] = fma2(h3.x, ua.x, acc2[3][0]);
            acc2[3][1] = fma2(h3.x, ua.y, acc2[3][1]);

            acc2[0][0] = fma2(h0.y, ub.x, acc2[0][0]);
            acc2[0][1] = fma2(h0.y, ub.y, acc2[0][1]);
            acc2[1][0] = fma2(h1.y, ub.x, acc2[1][0]);
            acc2[1][1] = fma2(h1.y, ub.y, acc2[1][1]);
            acc2[2][0] = fma2(h2.y, ub.x, acc2[2][0]);
            acc2[2][1] = fma2(h2.y, ub.y, acc2[2][1]);
            acc2[3][0] = fma2(h3.y, ub.x, acc2[3][0]);
            acc2[3][1] = fma2(h3.y, ub.y, acc2[3][1]);
        }

        // publish z tile (transposed [c][b])
#pragma unroll
        for (int i = 0; i < 4; i++) {
            z_s[(c0i + 0) * ZS + b0 + i] = hsum2(acc2[i][0]);
            z_s[(c0i + 1) * ZS + b0 + i] = hsum2(acc2[i][1]);
        }
        __syncthreads();

        // gates: 512 (b,jj) pairs, 2 per thread
#pragma unroll
        for (int pp = 0; pp < 2; pp++) {
            int p  = tid + pp * 256;
            int b  = p >> 3, jj = p & 7;
            float zi = z_s[(0  + jj) * ZS + b];
            float zf = z_s[(8  + jj) * ZS + b];
            float zg = z_s[(16 + jj) * ZS + b];
            float zo = z_s[(24 + jj) * ZS + b];
            float cold = c_s[p];
            float ig = sigmoidf_fast(zi);
            float fg = sigmoidf_fast(zf);
            float gg = tanhf(zg);
            float og = sigmoidf_fast(zo);
            float cn = fg * cold + ig * gg;
            float hn = og * tanhf(cn);
            c_s[p] = cn;
            int j = j0 + jj;
            __stcg(&hbuf_w[b * Hh + j], hn);
            int tout = dir ? (Tt - 1 - step) : step;
            out[((size_t)b * Tt + tout) * (2 * Hh) + dir * Hh + j] = hn;
            if (step == Tt - 1) {
                hT[b * 2 * Hh + dir * Hh + j] = hn;
                cT[b * 2 * Hh + dir * Hh + j] = cn;
            }
        }

        // grid barrier: fence, arrive (atomic), acquire-poll (plain L2 load)
        __threadfence();
        __syncthreads();
        if (tid == 0) {
            atomicAdd(&g_bar, 1u);
            unsigned target = (unsigned)(step + 1) * gridDim.x;
            unsigned v;
            do {
                asm volatile("ld.acquire.gpu.global.u32 %0, [%1];"
                             : "=r"(v) : "l"(&g_bar) : "memory");
                if (v >= target) break;
                __nanosleep(32);
            } while (true);
        }
        __syncthreads();
    }
}

// =================================================================================
extern "C" void kernel_launch(void* const* d_in, const int* in_sizes, int n_in,
                              void* d_out, int out_size)
{
    const int*   tokens = (const int*)  d_in[0];
    const float* h0_fw  = (const float*)d_in[1];
    const float* c0_fw  = (const float*)d_in[2];
    const float* h0_bw  = (const float*)d_in[3];
    const float* c0_bw  = (const float*)d_in[4];
    const float* emb    = (const float*)d_in[5];
    const float* W_fw   = (const float*)d_in[6];
    const float* U_fw   = (const float*)d_in[7];
    const float* b_fw   = (const float*)d_in[8];
    const float* W_bw   = (const float*)d_in[9];
    const float* U_bw   = (const float*)d_in[10];
    const float* b_bw   = (const float*)d_in[11];

    float* out = (float*)d_out;                       // [B,T,2H]
    float* hT  = out + (size_t)Bb * Tt * 2 * Hh;      // [B,2H]
    float* cT  = hT + (size_t)Bb * 2 * Hh;            // [B,2H]

    gemm_in<<<dim3(256, 64), 256>>>(tokens, emb, W_fw, b_fw, W_bw, b_bw);
    init_kernel<<<128, 256>>>(h0_fw, h0_bw);

    cudaFuncSetAttribute(lstm_scan, cudaFuncAttributeMaxDynamicSharedMemorySize,
                         SCAN_SMEM_BYTES);
    lstm_scan<<<128, 256, SCAN_SMEM_BYTES>>>(U_fw, U_bw, c0_fw, c0_bw, out, hT, cT);
}

// round 4
// speedup vs baseline: 1.2556x; 1.2556x over previous
#include <cuda_runtime.h>
#include <math.h>

#define Vv 34004
#define Ee 300
#define Hh 512
#define Bb 64
#define Tt 512
#define G4H 2048
#define BH (Bb * Hh)

// ---------------- scratch (device globals; no runtime allocation) ----------------
__device__ float g_xzf[67108864];      // [T][B][4H]  fw pre-activations
__device__ float g_xzb[67108864];      // [T][B][4H]  bw pre-activations (scan order)
__device__ float g_h[2 * 2 * BH];      // ping-pong: [buf][dir][H][B]  (k-major!)
__device__ unsigned g_bar;             // grid barrier counter (monotonic per launch)

// =================================================================================
// Phase A: xz[t,b,:] = emb[tokens[b,t]] @ W + bias   (both directions)
// Tiled FP32 GEMM (R2 version — best known). BM=128, BN=64, BK=16, 256 thr,
// 8x4 micro-tile, double-buffered smem.
// =================================================================================
__global__ __launch_bounds__(256) void gemm_in(
    const int* __restrict__ tokens, const float* __restrict__ emb,
    const float* __restrict__ W_fw, const float* __restrict__ b_fw,
    const float* __restrict__ W_bw, const float* __restrict__ b_bw)
{
    __shared__ __align__(16) float a_s[2][16][128];   // [buf][kk][r]
    __shared__ __align__(16) float w_s[2][16][64];    // [buf][kk][n]
    __shared__ int tok_s[128];

    const int tid = threadIdx.x;
    const int m0 = blockIdx.x * 128;
    const int nb = blockIdx.y;

    if (tid < 128) {
        int m = m0 + tid;
        int t = m >> 6, b = m & 63;
        tok_s[tid] = tokens[b * Tt + t];
    }

    const bool bw = (nb >= 32);
    const float* __restrict__ W    = bw ? W_bw : W_fw;
    const float* __restrict__ bias = bw ? b_bw : b_fw;
    const int n0 = (bw ? nb - 32 : nb) * 64;

    const int ry = tid >> 4;
    const int cx = tid & 15;

    const int ar  = tid >> 1;
    const int ak0 = (tid & 1) * 8;
    const int wk  = tid >> 4;
    const int wn  = (tid & 15) * 4;

    float acc[8][4];
#pragma unroll
    for (int i = 0; i < 8; i++)
#pragma unroll
        for (int j = 0; j < 4; j++) acc[i][j] = 0.f;

    __syncthreads();

    float4 areg0, areg1, wreg;
    const int NT = 19;  // ceil(300/16)

    {
        const float* src = emb + (size_t)tok_s[ar] * Ee + ak0;
        areg0 = *(const float4*)(src + 0);
        areg1 = *(const float4*)(src + 4);
        wreg  = *(const float4*)(W + (size_t)wk * G4H + n0 + wn);
        a_s[0][ak0 + 0][ar] = areg0.x; a_s[0][ak0 + 1][ar] = areg0.y;
        a_s[0][ak0 + 2][ar] = areg0.z; a_s[0][ak0 + 3][ar] = areg0.w;
        a_s[0][ak0 + 4][ar] = areg1.x; a_s[0][ak0 + 5][ar] = areg1.y;
        a_s[0][ak0 + 6][ar] = areg1.z; a_s[0][ak0 + 7][ar] = areg1.w;
        *(float4*)&w_s[0][wk][wn] = wreg;
    }
    __syncthreads();

    for (int kt = 0; kt < NT; kt++) {
        const int cur = kt & 1, nxt = cur ^ 1;

        if (kt + 1 < NT) {
            int k0 = (kt + 1) * 16;
            const float* src = emb + (size_t)tok_s[ar] * Ee + k0 + ak0;
            int ka = k0 + ak0;
            areg0 = (ka + 4 <= Ee) ? *(const float4*)(src + 0) : make_float4(0, 0, 0, 0);
            areg1 = (ka + 8 <= Ee) ? *(const float4*)(src + 4) : make_float4(0, 0, 0, 0);
            int kw = k0 + wk;
            wreg = (kw < Ee) ? *(const float4*)(W + (size_t)kw * G4H + n0 + wn)
                             : make_float4(0, 0, 0, 0);
        }

#pragma unroll
        for (int kk = 0; kk < 16; kk++) {
            float4 av0 = *(const float4*)&a_s[cur][kk][ry * 8];
            float4 av1 = *(const float4*)&a_s[cur][kk][ry * 8 + 4];
            float4 wv  = *(const float4*)&w_s[cur][kk][cx * 4];
            float a[8] = {av0.x, av0.y, av0.z, av0.w, av1.x, av1.y, av1.z, av1.w};
            float w[4] = {wv.x, wv.y, wv.z, wv.w};
#pragma unroll
            for (int i = 0; i < 8; i++)
#pragma unroll
                for (int j = 0; j < 4; j++) acc[i][j] += a[i] * w[j];
        }

        if (kt + 1 < NT) {
            a_s[nxt][ak0 + 0][ar] = areg0.x; a_s[nxt][ak0 + 1][ar] = areg0.y;
            a_s[nxt][ak0 + 2][ar] = areg0.z; a_s[nxt][ak0 + 3][ar] = areg0.w;
            a_s[nxt][ak0 + 4][ar] = areg1.x; a_s[nxt][ak0 + 5][ar] = areg1.y;
            a_s[nxt][ak0 + 6][ar] = areg1.z; a_s[nxt][ak0 + 7][ar] = areg1.w;
            *(float4*)&w_s[nxt][wk][wn] = wreg;
        }
        __syncthreads();
    }

    float4 bv = *(const float4*)(bias + n0 + cx * 4);
#pragma unroll
    for (int i = 0; i < 8; i++) {
        int m = m0 + ry * 8 + i;
        int t = m >> 6, b = m & 63;
        size_t row = bw ? ((size_t)(Tt - 1 - t) * Bb + b) : (size_t)m;
        float* dst = (bw ? g_xzb : g_xzf) + row * G4H + n0 + cx * 4;
        float4 o;
        o.x = acc[i][0] + bv.x;
        o.y = acc[i][1] + bv.y;
        o.z = acc[i][2] + bv.z;
        o.w = acc[i][3] + bv.w;
        *(float4*)dst = o;
    }
}

// =================================================================================
// init: reset barrier, seed h buf0 from h0 (transposed to [H][B] layout)
// =================================================================================
__global__ void init_kernel(const float* __restrict__ h0_fw,
                            const float* __restrict__ h0_bw)
{
    int i = blockIdx.x * blockDim.x + threadIdx.x;
    if (i == 0) g_bar = 0u;
    if (i < BH) {
        int j = i >> 6, b = i & 63;           // write index i = j*64 + b
        g_h[i]      = h0_fw[b * Hh + j];      // buf0, dir0
        g_h[BH + i] = h0_bw[b * Hh + j];      // buf0, dir1
    }
}

__device__ __forceinline__ float sigmoidf_fast(float x) {
    return __fdividef(1.f, 1.f + __expf(-x));
}

// =================================================================================
// Phase B: persistent bidirectional LSTM scan — smem-traffic-minimized.
// 128 CTAs: dir = blk>>6, jblk = blk&63 -> 8 hidden units -> 32 z-columns.
// Thread decomposition: 4 k-partitions x 8 batch-groups x 8 col-groups.
// Each thread: 8 batches x 4 cols micro-tile over K/4=128 -> 1.5 B smem / FMA.
// SMEM: U [512][32], h [512][64] (k-major, conflict-free), z partials [32][260],
//       c state [512]. Ping-pong h in L2 ([H][B] layout), acquire-poll barrier.
// =================================================================================
#define ZP 260
#define SCAN_SMEM_FLOATS (512 * 32 + 512 * 64 + 32 * ZP + 512)
#define SCAN_SMEM_BYTES  (SCAN_SMEM_FLOATS * 4)

__global__ __launch_bounds__(256, 1) void lstm_scan(
    const float* __restrict__ U_fw, const float* __restrict__ U_bw,
    const float* __restrict__ c0_fw, const float* __restrict__ c0_bw,
    float* __restrict__ out, float* __restrict__ hT, float* __restrict__ cT)
{
    extern __shared__ __align__(16) float sm[];
    float* U_s = sm;                    // [k][c]  (stride 32)
    float* h_s = U_s + 512 * 32;        // [k][b]  (stride 64)
    float* z_s = h_s + 512 * 64;        // [c][ZP]: partials at c*ZP + kp*64 + b
    float* c_s = z_s + 32 * ZP;         // [512]   (b*8 + jj)

    const int tid  = threadIdx.x;
    const int dir  = blockIdx.x >> 6;
    const int jblk = blockIdx.x & 63;
    const int j0   = jblk * 8;

    const float* __restrict__ U  = dir ? U_bw : U_fw;
    const float* __restrict__ c0 = dir ? c0_bw : c0_fw;
    const float* __restrict__ xz = dir ? g_xzb : g_xzf;

    // persistent U slice: U_s[k*32 + c], c -> gate=c>>3, jj=c&7
    for (int i = tid; i < 512 * 32; i += 256) {
        int k = i >> 5, c = i & 31;
        U_s[i] = U[(size_t)k * G4H + (c >> 3) * Hh + j0 + (c & 7)];
    }
    for (int i = tid; i < 512; i += 256)
        c_s[i] = c0[(i >> 3) * Hh + j0 + (i & 7)];

    // GEMM decomposition
    const int kp = tid >> 6;            // 0..3 k-partition
    const int g  = tid & 63;
    const int bg = g >> 3;              // 0..7
    const int cg = g & 7;               // 0..7
    const int b0 = bg * 8;
    const int c0g = cg * 4;
    const int kbase = kp * 128;

    // gate-phase identities (2 outputs per thread)
    int gb[2], gj[2];
#pragma unroll
    for (int pp = 0; pp < 2; pp++) {
        int p = tid + pp * 256;
        gb[pp] = p >> 3;
        gj[pp] = p & 7;
    }

    for (int step = 0; step < Tt; step++) {
        const float* hbuf_r = g_h + (((step) & 1) * 2 + dir) * BH;
        float*       hbuf_w = g_h + (((step + 1) & 1) * 2 + dir) * BH;

        // issue xz DRAM loads FIRST (latency overlaps h staging + GEMM)
        float xzr[2][4];
#pragma unroll
        for (int pp = 0; pp < 2; pp++) {
            const float* row = xz + ((size_t)step * Bb + gb[pp]) * G4H + j0 + gj[pp];
#pragma unroll
            for (int gt = 0; gt < 4; gt++)
                xzr[pp][gt] = __ldcs(row + gt * Hh);
        }

        // stage h from L2 into h_s[k][b] (both are k-major: straight copy)
        {
            const float4* hsrc = (const float4*)hbuf_r;
#pragma unroll 4
            for (int i = tid; i < BH / 4; i += 256) {
                float4 v = __ldcg(hsrc + i);
                *(float4*)&h_s[i * 4] = v;
            }
        }
        __syncthreads();

        // z_partial = h[b0..b0+8, kbase..kbase+128] @ U[.., c0g..c0g+4]
        float acc[8][4];
#pragma unroll
        for (int i = 0; i < 8; i++)
#pragma unroll
            for (int j = 0; j < 4; j++) acc[i][j] = 0.f;

#pragma unroll 2
        for (int k = 0; k < 128; k += 4) {
#pragma unroll
            for (int kk = 0; kk < 4; kk++) {
                const int ka = kbase + k + kk;
                float4 h0 = *(const float4*)&h_s[ka * 64 + b0];
                float4 h1 = *(const float4*)&h_s[ka * 64 + b0 + 4];
                float4 uv = *(const float4*)&U_s[ka * 32 + c0g];
                float hv[8] = {h0.x, h0.y, h0.z, h0.w, h1.x, h1.y, h1.z, h1.w};
                float uu[4] = {uv.x, uv.y, uv.z, uv.w};
#pragma unroll
                for (int i = 0; i < 8; i++)
#pragma unroll
                    for (int j = 0; j < 4; j++) acc[i][j] += hv[i] * uu[j];
            }
        }

        // publish partials: z_s[c][kp*64 + b]
#pragma unroll
        for (int j = 0; j < 4; j++) {
            float* zd = &z_s[(c0g + j) * ZP + kp * 64 + b0];
            *(float4*)(zd)     = make_float4(acc[0][j], acc[1][j], acc[2][j], acc[3][j]);
            *(float4*)(zd + 4) = make_float4(acc[4][j], acc[5][j], acc[6][j], acc[7][j]);
        }
        __syncthreads();

        // gates: 512 (b,jj) pairs, 2 per thread; reduce 4 kp partials + xz
#pragma unroll
        for (int pp = 0; pp < 2; pp++) {
            const int b = gb[pp], jj = gj[pp];
            float zv[4];
#pragma unroll
            for (int gt = 0; gt < 4; gt++) {
                const float* zp = &z_s[(gt * 8 + jj) * ZP + b];
                zv[gt] = xzr[pp][gt] + ((zp[0] + zp[64]) + (zp[128] + zp[192]));
            }
            const int p = tid + pp * 256;
            float cold = c_s[p];
            float ig = sigmoidf_fast(zv[0]);
            float fg = sigmoidf_fast(zv[1]);
            float gg = tanhf(zv[2]);
            float og = sigmoidf_fast(zv[3]);
            float cn = fg * cold + ig * gg;
            float hn = og * tanhf(cn);
            c_s[p] = cn;
            const int j = j0 + jj;
            __stcg(&hbuf_w[j * 64 + b], hn);     // [H][B] layout
            int tout = dir ? (Tt - 1 - step) : step;
            out[((size_t)b * Tt + tout) * (2 * Hh) + dir * Hh + j] = hn;
            if (step == Tt - 1) {
                hT[b * 2 * Hh + dir * Hh + j] = hn;
                cT[b * 2 * Hh + dir * Hh + j] = cn;
            }
        }

        // grid barrier: fence, arrive (atomic), acquire-poll (plain L2 load)
        __threadfence();
        __syncthreads();
        if (tid == 0) {
            atomicAdd(&g_bar, 1u);
            unsigned target = (unsigned)(step + 1) * gridDim.x;
            unsigned v;
            do {
                asm volatile("ld.acquire.gpu.global.u32 %0, [%1];"
                             : "=r"(v) : "l"(&g_bar) : "memory");
                if (v >= target) break;
                __nanosleep(32);
            } while (true);
        }
        __syncthreads();
    }
}

// =================================================================================
extern "C" void kernel_launch(void* const* d_in, const int* in_sizes, int n_in,
                              void* d_out, int out_size)
{
    const int*   tokens = (const int*)  d_in[0];
    const float* h0_fw  = (const float*)d_in[1];
    const float* c0_fw  = (const float*)d_in[2];
    const float* h0_bw  = (const float*)d_in[3];
    const float* c0_bw  = (const float*)d_in[4];
    const float* emb    = (const float*)d_in[5];
    const float* W_fw   = (const float*)d_in[6];
    const float* U_fw   = (const float*)d_in[7];
    const float* b_fw   = (const float*)d_in[8];
    const float* W_bw   = (const float*)d_in[9];
    const float* U_bw   = (const float*)d_in[10];
    const float* b_bw   = (const float*)d_in[11];

    float* out = (float*)d_out;                       // [B,T,2H]
    float* hT  = out + (size_t)Bb * Tt * 2 * Hh;      // [B,2H]
    float* cT  = hT + (size_t)Bb * 2 * Hh;            // [B,2H]

    gemm_in<<<dim3(256, 64), 256>>>(tokens, emb, W_fw, b_fw, W_bw, b_bw);
    init_kernel<<<128, 256>>>(h0_fw, h0_bw);

    cudaFuncSetAttribute(lstm_scan, cudaFuncAttributeMaxDynamicSharedMemorySize,
                         SCAN_SMEM_BYTES);
    lstm_scan<<<128, 256, SCAN_SMEM_BYTES>>>(U_fw, U_bw, c0_fw, c0_bw, out, hT, cT);
}

// round 7
// speedup vs baseline: 1.4267x; 1.1363x over previous
#include <cuda_runtime.h>
#include <cuda_bf16.h>
#include <math.h>
#include <stdint.h>

#define Vv 34004
#define Ee 300
#define Hh 512
#define Bb 64
#define Tt 512
#define G4H 2048
#define BH (Bb * Hh)
#define MK 32768          // M total = B*T
#define KPAD 320          // K padded to 320

// ---------------- scratch (device globals; no runtime allocation) ----------------
__device__ float g_xzf[67108864];          // [T][B][4H] fw pre-activations
__device__ float g_xzb[67108864];          // [T][B][4H] bw pre-activations (scan order)
__device__ float g_h[2 * 2 * BH];          // ping-pong: [buf][dir][H][B] (k-major)
__device__ unsigned g_bar;                 // grid barrier counter
__device__ __nv_bfloat16 g_Ah[(size_t)MK * KPAD];   // emb-gathered A, hi split
__device__ __nv_bfloat16 g_Al[(size_t)MK * KPAD];   // lo split
__device__ __nv_bfloat16 g_Bh[(size_t)4096 * KPAD]; // W^T (B[n][k]), hi split (fw||bw)
__device__ __nv_bfloat16 g_Bl[(size_t)4096 * KPAD];

// ---------------- PTX helpers (sm_80-class: compile under compute_103) ----------
__device__ __forceinline__ uint32_t smem_u32(const void* p) {
    uint32_t a;
    asm("{ .reg .u64 t; cvta.to.shared.u64 t, %1; cvt.u32.u64 %0, t; }"
        : "=r"(a) : "l"(p));
    return a;
}
#define CP_ASYNC16(s, g) \
    asm volatile("cp.async.cg.shared.global [%0], [%1], 16;" :: "r"(s), "l"(g))
#define CP_COMMIT() asm volatile("cp.async.commit_group;" ::: "memory")
#define CP_WAIT1()  asm volatile("cp.async.wait_group 1;" ::: "memory")
#define CP_WAIT0()  asm volatile("cp.async.wait_group 0;" ::: "memory")

#define LDSM4(r0, r1, r2, r3, addr) \
    asm volatile("ldmatrix.sync.aligned.m8n8.x4.shared.b16 {%0,%1,%2,%3}, [%4];" \
                 : "=r"(r0), "=r"(r1), "=r"(r2), "=r"(r3) : "r"(addr))

#define MMA16816(c, a0, a1, a2, a3, b0, b1) \
    asm volatile("mma.sync.aligned.m16n8k16.row.col.f32.bf16.bf16.f32 " \
                 "{%0,%1,%2,%3},{%4,%5,%6,%7},{%8,%9},{%0,%1,%2,%3};" \
                 : "+f"((c)[0]), "+f"((c)[1]), "+f"((c)[2]), "+f"((c)[3]) \
                 : "r"(a0), "r"(a1), "r"(a2), "r"(a3), "r"(b0), "r"(b1))

// =================================================================================
// prep_A: gather emb rows, split fp32 -> bf16 hi/lo, pad K to 320
// =================================================================================
__global__ void prep_A(const int* __restrict__ tokens, const float* __restrict__ emb) {
    size_t idx = (size_t)blockIdx.x * blockDim.x + threadIdx.x;
    if (idx >= (size_t)MK * KPAD) return;
    int m = (int)(idx / KPAD), k = (int)(idx - (size_t)m * KPAD);
    int t = m >> 6, b = m & 63;
    int tok = tokens[b * Tt + t];
    float v = (k < Ee) ? emb[(size_t)tok * Ee + k] : 0.f;
    __nv_bfloat16 hi = __float2bfloat16(v);
    g_Ah[idx] = hi;
    g_Al[idx] = __float2bfloat16(v - __bfloat162float(hi));
}

// =================================================================================
// prep_B: B[n][k] = W[k][n] (fw n<2048, bw n>=2048), split hi/lo, pad K to 320
// =================================================================================
__global__ void prep_B(const float* __restrict__ W_fw, const float* __restrict__ W_bw) {
    size_t idx = (size_t)blockIdx.x * blockDim.x + threadIdx.x;
    if (idx >= (size_t)4096 * KPAD) return;
    int n = (int)(idx / KPAD), k = (int)(idx - (size_t)n * KPAD);
    int dir = n >> 11, nn = n & 2047;
    const float* W = dir ? W_bw : W_fw;
    float v = (k < Ee) ? W[(size_t)k * G4H + nn] : 0.f;
    __nv_bfloat16 hi = __float2bfloat16(v);
    g_Bh[idx] = hi;
    g_Bl[idx] = __float2bfloat16(v - __bfloat162float(hi));
}

// =================================================================================
// gemm_hmma: xz = A @ B^T + bias via mma.sync bf16 split (3 products, f32 accum).
// Per CTA: M=128 (blockIdx.y), N=64 (blockIdx.x). K=320 in 5 chunks of 64,
// cp.async double-buffered. 8 warps: 4 m-warps x 2 n-warps, warp tile 32x32.
// SMEM tiles padded to 72 bf16 (144 B) row stride -> conflict-free ldmatrix.
// =================================================================================
#define KC 64
#define SROW 144                       // bytes per smem row (72 bf16)
#define SZ_A (128 * SROW)              // 18432
#define SZ_B (64 * SROW)               // 9216
#define BUFSZ (2 * SZ_A + 2 * SZ_B)    // 55296
#define OFF_AH 0
#define OFF_AL SZ_A
#define OFF_BH (2 * SZ_A)
#define OFF_BL (2 * SZ_A + SZ_B)
#define GEMM_SMEM (2 * BUFSZ)          // 110592

__global__ __launch_bounds__(256, 1) void gemm_hmma(
    const float* __restrict__ b_fw, const float* __restrict__ b_bw)
{
    extern __shared__ char smg[];
    const uint32_t base = smem_u32(smg);

    const int tid  = threadIdx.x;
    const int wid  = tid >> 5;
    const int lane = tid & 31;
    const int n0 = blockIdx.x * 64;
    const int m0 = blockIdx.y * 128;

    const int mw = (wid >> 1) * 32;    // warp m offset in tile
    const int nw = (wid & 1) * 32;     // warp n offset in tile

    // cp.async loader indices (12 x 16B per thread per chunk)
    const int la_row = tid >> 1;                 // 2 threads per A row: 0..127
    const int la_g0  = (tid & 1) * 4;            // groups 0-3 or 4-7
    const int lb_row = tid >> 2;                 // 4 threads per B row: 0..63
    const int lb_g0  = (tid & 3) * 2;            // groups {0,1},{2,3},{4,5},{6,7}

    auto load_chunk = [&](int ch, int buf) {
        const int k0 = ch * KC;
        const uint32_t bb = base + buf * BUFSZ;
        // A hi/lo: 4 groups each
        {
            const size_t gsrc = (size_t)(m0 + la_row) * KPAD + k0 + la_g0 * 8;
            const uint32_t sdst = bb + la_row * SROW + la_g0 * 16;
#pragma unroll
            for (int u = 0; u < 4; u++) {
                CP_ASYNC16(sdst + OFF_AH + u * 16, g_Ah + gsrc + u * 8);
                CP_ASYNC16(sdst + OFF_AL + u * 16, g_Al + gsrc + u * 8);
            }
        }
        // B hi/lo: 2 groups each
        {
            const size_t gsrc = (size_t)(n0 + lb_row) * KPAD + k0 + lb_g0 * 8;
            const uint32_t sdst = bb + lb_row * SROW + lb_g0 * 16;
#pragma unroll
            for (int u = 0; u < 2; u++) {
                CP_ASYNC16(sdst + OFF_BH + u * 16, g_Bh + gsrc + u * 8);
                CP_ASYNC16(sdst + OFF_BL + u * 16, g_Bl + gsrc + u * 8);
            }
        }
        CP_COMMIT();
    };

    float acc[8][4];
#pragma unroll
    for (int i = 0; i < 8; i++)
#pragma unroll
        for (int j = 0; j < 4; j++) acc[i][j] = 0.f;

    // ldmatrix per-thread address offsets (bytes)
    const uint32_t a_off = (uint32_t)((lane & 15) * SROW + (lane >> 4) * 16);
    const uint32_t b_off = (uint32_t)(((lane & 7) + ((lane >> 4) & 1) * 8) * SROW
                                      + ((lane >> 3) & 1) * 16);

    load_chunk(0, 0);

    const int NCH = KPAD / KC;  // 5
    for (int ch = 0; ch < NCH; ch++) {
        const int buf = ch & 1;
        if (ch + 1 < NCH) {
            load_chunk(ch + 1, (ch + 1) & 1);
            CP_WAIT1();
        } else {
            CP_WAIT0();
        }
        __syncthreads();

        const uint32_t bb = base + buf * BUFSZ;
        const uint32_t aH = bb + OFF_AH + mw * SROW + a_off;
        const uint32_t aL = bb + OFF_AL + mw * SROW + a_off;
        const uint32_t bH = bb + OFF_BH + nw * SROW + b_off;
        const uint32_t bL = bb + OFF_BL + nw * SROW + b_off;

#pragma unroll
        for (int ks = 0; ks < KC / 16; ks++) {
            const uint32_t kb = ks * 32;
            uint32_t ah0[4], ah1[4], al0[4], al1[4];
            LDSM4(ah0[0], ah0[1], ah0[2], ah0[3], aH + kb);
            LDSM4(ah1[0], ah1[1], ah1[2], ah1[3], aH + 16 * SROW + kb);
            LDSM4(al0[0], al0[1], al0[2], al0[3], aL + kb);
            LDSM4(al1[0], al1[1], al1[2], al1[3], aL + 16 * SROW + kb);
            uint32_t bh[8], bl[8];
            LDSM4(bh[0], bh[1], bh[2], bh[3], bH + kb);
            LDSM4(bh[4], bh[5], bh[6], bh[7], bH + 16 * SROW + kb);
            LDSM4(bl[0], bl[1], bl[2], bl[3], bL + kb);
            LDSM4(bl[4], bl[5], bl[6], bl[7], bL + 16 * SROW + kb);

#pragma unroll
            for (int mi = 0; mi < 2; mi++) {
                const uint32_t* ah = mi ? ah1 : ah0;
                const uint32_t* al = mi ? al1 : al0;
#pragma unroll
                for (int ni = 0; ni < 4; ni++) {
                    float* c = acc[mi * 4 + ni];
                    const uint32_t bh0 = bh[ni * 2], bh1 = bh[ni * 2 + 1];
                    const uint32_t bl0 = bl[ni * 2], bl1 = bl[ni * 2 + 1];
                    MMA16816(c, ah[0], ah[1], ah[2], ah[3], bh0, bh1);
                    MMA16816(c, ah[0], ah[1], ah[2], ah[3], bl0, bl1);
                    MMA16816(c, al[0], al[1], al[2], al[3], bh0, bh1);
                }
            }
        }
        __syncthreads();
    }

    // ---- epilogue: add bias, store to g_xzf / g_xzb (t-reversed for bw) ----
    const int dir = n0 >> 11;
    const int nn0 = n0 & 2047;
    const float* bias = dir ? b_bw : b_fw;
    const int qr = lane >> 2;          // quad row 0..7
    const int qc = (lane & 3) * 2;     // col pair base

#pragma unroll
    for (int mi = 0; mi < 2; mi++) {
#pragma unroll
        for (int ni = 0; ni < 4; ni++) {
            const float* c = acc[mi * 4 + ni];
            const int ncol = nw + ni * 8 + qc;       // 0..63 within tile
            const float bv0 = bias[nn0 + ncol];
            const float bv1 = bias[nn0 + ncol + 1];
#pragma unroll
            for (int half = 0; half < 2; half++) {
                const int m = m0 + mw + mi * 16 + qr + half * 8;
                const int t = m >> 6, b = m & 63;
                float* dst = dir
                    ? (g_xzb + ((size_t)(Tt - 1 - t) * Bb + b) * G4H + nn0 + ncol)
                    : (g_xzf + (size_t)m * G4H + nn0 + ncol);
                float2 o;
                o.x = c[half * 2 + 0] + bv0;
                o.y = c[half * 2 + 1] + bv1;
                *(float2*)dst = o;
            }
        }
    }
}

// =================================================================================
// init: reset barrier, seed h buf0 from h0 (transposed to [H][B] layout)
// =================================================================================
__global__ void init_kernel(const float* __restrict__ h0_fw,
                            const float* __restrict__ h0_bw)
{
    int i = blockIdx.x * blockDim.x + threadIdx.x;
    if (i == 0) g_bar = 0u;
    if (i < BH) {
        int j = i >> 6, b = i & 63;
        g_h[i]      = h0_fw[b * Hh + j];
        g_h[BH + i] = h0_bw[b * Hh + j];
    }
}

__device__ __forceinline__ float sigmoidf_fast(float x) {
    return __fdividef(1.f, 1.f + __expf(-x));
}

// =================================================================================
// Phase B: persistent bidirectional LSTM scan (unchanged — at FFMA floor).
// =================================================================================
#define ZP 260
#define SCAN_SMEM_FLOATS (512 * 32 + 512 * 64 + 32 * ZP + 512)
#define SCAN_SMEM_BYTES  (SCAN_SMEM_FLOATS * 4)

__global__ __launch_bounds__(256, 1) void lstm_scan(
    const float* __restrict__ U_fw, const float* __restrict__ U_bw,
    const float* __restrict__ c0_fw, const float* __restrict__ c0_bw,
    float* __restrict__ out, float* __restrict__ hT, float* __restrict__ cT)
{
    extern __shared__ __align__(16) float sml[];
    float* U_s = sml;                   // [k][c]  (stride 32)
    float* h_s = U_s + 512 * 32;        // [k][b]  (stride 64)
    float* z_s = h_s + 512 * 64;        // [c][ZP]: partials at c*ZP + kp*64 + b
    float* c_s = z_s + 32 * ZP;         // [512]   (b*8 + jj)

    const int tid  = threadIdx.x;
    const int dir  = blockIdx.x >> 6;
    const int jblk = blockIdx.x & 63;
    const int j0   = jblk * 8;

    const float* __restrict__ U  = dir ? U_bw : U_fw;
    const float* __restrict__ c0 = dir ? c0_bw : c0_fw;
    const float* __restrict__ xz = dir ? g_xzb : g_xzf;

    for (int i = tid; i < 512 * 32; i += 256) {
        int k = i >> 5, c = i & 31;
        U_s[i] = U[(size_t)k * G4H + (c >> 3) * Hh + j0 + (c & 7)];
    }
    for (int i = tid; i < 512; i += 256)
        c_s[i] = c0[(i >> 3) * Hh + j0 + (i & 7)];

    const int kp = tid >> 6;
    const int g  = tid & 63;
    const int bg = g >> 3;
    const int cg = g & 7;
    const int b0 = bg * 8;
    const int c0g = cg * 4;
    const int kbase = kp * 128;

    int gb[2], gj[2];
#pragma unroll
    for (int pp = 0; pp < 2; pp++) {
        int p = tid + pp * 256;
        gb[pp] = p >> 3;
        gj[pp] = p & 7;
    }

    for (int step = 0; step < Tt; step++) {
        const float* hbuf_r = g_h + (((step) & 1) * 2 + dir) * BH;
        float*       hbuf_w = g_h + (((step + 1) & 1) * 2 + dir) * BH;

        float xzr[2][4];
#pragma unroll
        for (int pp = 0; pp < 2; pp++) {
            const float* row = xz + ((size_t)step * Bb + gb[pp]) * G4H + j0 + gj[pp];
#pragma unroll
            for (int gt = 0; gt < 4; gt++)
                xzr[pp][gt] = __ldcs(row + gt * Hh);
        }

        {
            const float4* hsrc = (const float4*)hbuf_r;
#pragma unroll 4
            for (int i = tid; i < BH / 4; i += 256) {
                float4 v = __ldcg(hsrc + i);
                *(float4*)&h_s[i * 4] = v;
            }
        }
        __syncthreads();

        float acc[8][4];
#pragma unroll
        for (int i = 0; i < 8; i++)
#pragma unroll
            for (int j = 0; j < 4; j++) acc[i][j] = 0.f;

#pragma unroll 2
        for (int k = 0; k < 128; k += 4) {
#pragma unroll
            for (int kk = 0; kk < 4; kk++) {
                const int ka = kbase + k + kk;
                float4 h0 = *(const float4*)&h_s[ka * 64 + b0];
                float4 h1 = *(const float4*)&h_s[ka * 64 + b0 + 4];
                float4 uv = *(const float4*)&U_s[ka * 32 + c0g];
                float hv[8] = {h0.x, h0.y, h0.z, h0.w, h1.x, h1.y, h1.z, h1.w};
                float uu[4] = {uv.x, uv.y, uv.z, uv.w};
#pragma unroll
                for (int i = 0; i < 8; i++)
#pragma unroll
                    for (int j = 0; j < 4; j++) acc[i][j] += hv[i] * uu[j];
            }
        }

#pragma unroll
        for (int j = 0; j < 4; j++) {
            float* zd = &z_s[(c0g + j) * ZP + kp * 64 + b0];
            *(float4*)(zd)     = make_float4(acc[0][j], acc[1][j], acc[2][j], acc[3][j]);
            *(float4*)(zd + 4) = make_float4(acc[4][j], acc[5][j], acc[6][j], acc[7][j]);
        }
        __syncthreads();

#pragma unroll
        for (int pp = 0; pp < 2; pp++) {
            const int b = gb[pp], jj = gj[pp];
            float zv[4];
#pragma unroll
            for (int gt = 0; gt < 4; gt++) {
                const float* zp = &z_s[(gt * 8 + jj) * ZP + b];
                zv[gt] = xzr[pp][gt] + ((zp[0] + zp[64]) + (zp[128] + zp[192]));
            }
            const int p = tid + pp * 256;
            float cold = c_s[p];
            float ig = sigmoidf_fast(zv[0]);
            float fg = sigmoidf_fast(zv[1]);
            float gg = tanhf(zv[2]);
            float og = sigmoidf_fast(zv[3]);
            float cn = fg * cold + ig * gg;
            float hn = og * tanhf(cn);
            c_s[p] = cn;
            const int j = j0 + jj;
            __stcg(&hbuf_w[j * 64 + b], hn);
            int tout = dir ? (Tt - 1 - step) : step;
            out[((size_t)b * Tt + tout) * (2 * Hh) + dir * Hh + j] = hn;
            if (step == Tt - 1) {
                hT[b * 2 * Hh + dir * Hh + j] = hn;
                cT[b * 2 * Hh + dir * Hh + j] = cn;
            }
        }

        __threadfence();
        __syncthreads();
        if (tid == 0) {
            atomicAdd(&g_bar, 1u);
            unsigned target = (unsigned)(step + 1) * gridDim.x;
            unsigned v;
            do {
                asm volatile("ld.acquire.gpu.global.u32 %0, [%1];"
                             : "=r"(v) : "l"(&g_bar) : "memory");
                if (v >= target) break;
                __nanosleep(32);
            } while (true);
        }
        __syncthreads();
    }
}

// =================================================================================
extern "C" void kernel_launch(void* const* d_in, const int* in_sizes, int n_in,
                              void* d_out, int out_size)
{
    const int*   tokens = (const int*)  d_in[0];
    const float* h0_fw  = (const float*)d_in[1];
    const float* c0_fw  = (const float*)d_in[2];
    const float* h0_bw  = (const float*)d_in[3];
    const float* c0_bw  = (const float*)d_in[4];
    const float* emb    = (const float*)d_in[5];
    const float* W_fw   = (const float*)d_in[6];
    const float* U_fw   = (const float*)d_in[7];
    const float* b_fw   = (const float*)d_in[8];
    const float* W_bw   = (const float*)d_in[9];
    const float* U_bw   = (const float*)d_in[10];
    const float* b_bw   = (const float*)d_in[11];

    float* out = (float*)d_out;                       // [B,T,2H]
    float* hT  = out + (size_t)Bb * Tt * 2 * Hh;      // [B,2H]
    float* cT  = hT + (size_t)Bb * 2 * Hh;            // [B,2H]

    // prep: split inputs to bf16 hi/lo scratch
    {
        size_t na = (size_t)MK * KPAD;
        prep_A<<<(unsigned)((na + 255) / 256), 256>>>(tokens, emb);
        size_t nb = (size_t)4096 * KPAD;
        prep_B<<<(unsigned)((nb + 255) / 256), 256>>>(W_fw, W_bw);
    }
    init_kernel<<<128, 256>>>(h0_fw, h0_bw);

    // tensor-core input GEMM (mma.sync bf16 split)
    cudaFuncSetAttribute(gemm_hmma, cudaFuncAttributeMaxDynamicSharedMemorySize,
                         GEMM_SMEM);
    gemm_hmma<<<dim3(64, 256), 256, GEMM_SMEM>>>(b_fw, b_bw);

    // persistent LSTM scan
    cudaFuncSetAttribute(lstm_scan, cudaFuncAttributeMaxDynamicSharedMemorySize,
                         SCAN_SMEM_BYTES);
    lstm_scan<<<128, 256, SCAN_SMEM_BYTES>>>(U_fw, U_bw, c0_fw, c0_bw, out, hT, cT);
}

// round 8
// speedup vs baseline: 2.1984x; 1.5409x over previous
#include <cuda_runtime.h>
#include <cuda_bf16.h>
#include <math.h>
#include <stdint.h>

#define Vv 34004
#define Ee 300
#define Hh 512
#define Bb 64
#define Tt 512
#define G4H 2048
#define BH (Bb * Hh)
#define MK 32768          // M total = B*T
#define KPAD 320          // K padded to 320

// ---------------- scratch (device globals; no runtime allocation) ----------------
__device__ float g_xzf[67108864];          // [T][B][4H] fw pre-activations
__device__ float g_xzb[67108864];          // [T][B][4H] bw pre-activations (scan order)
__device__ __nv_bfloat16 g_hh[2 * 2 * BH]; // h hi split, ping-pong [buf][dir][b][H]
__device__ __nv_bfloat16 g_hl[2 * 2 * BH]; // h lo split
__device__ unsigned g_bar;                 // grid barrier counter
__device__ __nv_bfloat16 g_Ah[(size_t)MK * KPAD];   // emb-gathered A, hi split
__device__ __nv_bfloat16 g_Al[(size_t)MK * KPAD];   // lo split
__device__ __nv_bfloat16 g_Bh[(size_t)4096 * KPAD]; // W^T (B[n][k]), hi split (fw||bw)
__device__ __nv_bfloat16 g_Bl[(size_t)4096 * KPAD];

// ---------------- PTX helpers (sm_80-class: compile under compute_103) ----------
__device__ __forceinline__ uint32_t smem_u32(const void* p) {
    uint32_t a;
    asm("{ .reg .u64 t; cvta.to.shared.u64 t, %1; cvt.u32.u64 %0, t; }"
        : "=r"(a) : "l"(p));
    return a;
}
#define CP_ASYNC16(s, g) \
    asm volatile("cp.async.cg.shared.global [%0], [%1], 16;" :: "r"(s), "l"(g))
#define CP_COMMIT() asm volatile("cp.async.commit_group;" ::: "memory")
#define CP_WAIT1()  asm volatile("cp.async.wait_group 1;" ::: "memory")
#define CP_WAIT0()  asm volatile("cp.async.wait_group 0;" ::: "memory")

#define LDSM4(r0, r1, r2, r3, addr) \
    asm volatile("ldmatrix.sync.aligned.m8n8.x4.shared.b16 {%0,%1,%2,%3}, [%4];" \
                 : "=r"(r0), "=r"(r1), "=r"(r2), "=r"(r3) : "r"(addr))

#define MMA16816(c, a0, a1, a2, a3, b0, b1) \
    asm volatile("mma.sync.aligned.m16n8k16.row.col.f32.bf16.bf16.f32 " \
                 "{%0,%1,%2,%3},{%4,%5,%6,%7},{%8,%9},{%0,%1,%2,%3};" \
                 : "+f"((c)[0]), "+f"((c)[1]), "+f"((c)[2]), "+f"((c)[3]) \
                 : "r"(a0), "r"(a1), "r"(a2), "r"(a3), "r"(b0), "r"(b1))

// =================================================================================
// prep_A: gather emb rows, split fp32 -> bf16 hi/lo, pad K to 320
// =================================================================================
__global__ void prep_A(const int* __restrict__ tokens, const float* __restrict__ emb) {
    size_t idx = (size_t)blockIdx.x * blockDim.x + threadIdx.x;
    if (idx >= (size_t)MK * KPAD) return;
    int m = (int)(idx / KPAD), k = (int)(idx - (size_t)m * KPAD);
    int t = m >> 6, b = m & 63;
    int tok = tokens[b * Tt + t];
    float v = (k < Ee) ? emb[(size_t)tok * Ee + k] : 0.f;
    __nv_bfloat16 hi = __float2bfloat16(v);
    g_Ah[idx] = hi;
    g_Al[idx] = __float2bfloat16(v - __bfloat162float(hi));
}

// =================================================================================
// prep_B: B[n][k] = W[k][n] (fw n<2048, bw n>=2048), split hi/lo, pad K to 320
// =================================================================================
__global__ void prep_B(const float* __restrict__ W_fw, const float* __restrict__ W_bw) {
    size_t idx = (size_t)blockIdx.x * blockDim.x + threadIdx.x;
    if (idx >= (size_t)4096 * KPAD) return;
    int n = (int)(idx / KPAD), k = (int)(idx - (size_t)n * KPAD);
    int dir = n >> 11, nn = n & 2047;
    const float* W = dir ? W_bw : W_fw;
    float v = (k < Ee) ? W[(size_t)k * G4H + nn] : 0.f;
    __nv_bfloat16 hi = __float2bfloat16(v);
    g_Bh[idx] = hi;
    g_Bl[idx] = __float2bfloat16(v - __bfloat162float(hi));
}

// =================================================================================
// gemm_hmma: xz = A @ B^T + bias via mma.sync bf16 split (unchanged from R7)
// =================================================================================
#define KC 64
#define SROW 144
#define SZ_A (128 * SROW)
#define SZ_B (64 * SROW)
#define BUFSZ (2 * SZ_A + 2 * SZ_B)
#define OFF_AH 0
#define OFF_AL SZ_A
#define OFF_BH (2 * SZ_A)
#define OFF_BL (2 * SZ_A + SZ_B)
#define GEMM_SMEM (2 * BUFSZ)

__global__ __launch_bounds__(256, 1) void gemm_hmma(
    const float* __restrict__ b_fw, const float* __restrict__ b_bw)
{
    extern __shared__ char smg[];
    const uint32_t base = smem_u32(smg);

    const int tid  = threadIdx.x;
    const int wid  = tid >> 5;
    const int lane = tid & 31;
    const int n0 = blockIdx.x * 64;
    const int m0 = blockIdx.y * 128;

    const int mw = (wid >> 1) * 32;
    const int nw = (wid & 1) * 32;

    const int la_row = tid >> 1;
    const int la_g0  = (tid & 1) * 4;
    const int lb_row = tid >> 2;
    const int lb_g0  = (tid & 3) * 2;

    auto load_chunk = [&](int ch, int buf) {
        const int k0 = ch * KC;
        const uint32_t bb = base + buf * BUFSZ;
        {
            const size_t gsrc = (size_t)(m0 + la_row) * KPAD + k0 + la_g0 * 8;
            const uint32_t sdst = bb + la_row * SROW + la_g0 * 16;
#pragma unroll
            for (int u = 0; u < 4; u++) {
                CP_ASYNC16(sdst + OFF_AH + u * 16, g_Ah + gsrc + u * 8);
                CP_ASYNC16(sdst + OFF_AL + u * 16, g_Al + gsrc + u * 8);
            }
        }
        {
            const size_t gsrc = (size_t)(n0 + lb_row) * KPAD + k0 + lb_g0 * 8;
            const uint32_t sdst = bb + lb_row * SROW + lb_g0 * 16;
#pragma unroll
            for (int u = 0; u < 2; u++) {
                CP_ASYNC16(sdst + OFF_BH + u * 16, g_Bh + gsrc + u * 8);
                CP_ASYNC16(sdst + OFF_BL + u * 16, g_Bl + gsrc + u * 8);
            }
        }
        CP_COMMIT();
    };

    float acc[8][4];
#pragma unroll
    for (int i = 0; i < 8; i++)
#pragma unroll
        for (int j = 0; j < 4; j++) acc[i][j] = 0.f;

    const uint32_t a_off = (uint32_t)((lane & 15) * SROW + (lane >> 4) * 16);
    const uint32_t b_off = (uint32_t)(((lane & 7) + ((lane >> 4) & 1) * 8) * SROW
                                      + ((lane >> 3) & 1) * 16);

    load_chunk(0, 0);

    const int NCH = KPAD / KC;
    for (int ch = 0; ch < NCH; ch++) {
        const int buf = ch & 1;
        if (ch + 1 < NCH) {
            load_chunk(ch + 1, (ch + 1) & 1);
            CP_WAIT1();
        } else {
            CP_WAIT0();
        }
        __syncthreads();

        const uint32_t bb = base + buf * BUFSZ;
        const uint32_t aH = bb + OFF_AH + mw * SROW + a_off;
        const uint32_t aL = bb + OFF_AL + mw * SROW + a_off;
        const uint32_t bH = bb + OFF_BH + nw * SROW + b_off;
        const uint32_t bL = bb + OFF_BL + nw * SROW + b_off;

#pragma unroll
        for (int ks = 0; ks < KC / 16; ks++) {
            const uint32_t kb = ks * 32;
            uint32_t ah0[4], ah1[4], al0[4], al1[4];
            LDSM4(ah0[0], ah0[1], ah0[2], ah0[3], aH + kb);
            LDSM4(ah1[0], ah1[1], ah1[2], ah1[3], aH + 16 * SROW + kb);
            LDSM4(al0[0], al0[1], al0[2], al0[3], aL + kb);
            LDSM4(al1[0], al1[1], al1[2], al1[3], aL + 16 * SROW + kb);
            uint32_t bh[8], bl[8];
            LDSM4(bh[0], bh[1], bh[2], bh[3], bH + kb);
            LDSM4(bh[4], bh[5], bh[6], bh[7], bH + 16 * SROW + kb);
            LDSM4(bl[0], bl[1], bl[2], bl[3], bL + kb);
            LDSM4(bl[4], bl[5], bl[6], bl[7], bL + 16 * SROW + kb);

#pragma unroll
            for (int mi = 0; mi < 2; mi++) {
                const uint32_t* ah = mi ? ah1 : ah0;
                const uint32_t* al = mi ? al1 : al0;
#pragma unroll
                for (int ni = 0; ni < 4; ni++) {
                    float* c = acc[mi * 4 + ni];
                    const uint32_t bh0 = bh[ni * 2], bh1 = bh[ni * 2 + 1];
                    const uint32_t bl0 = bl[ni * 2], bl1 = bl[ni * 2 + 1];
                    MMA16816(c, ah[0], ah[1], ah[2], ah[3], bh0, bh1);
                    MMA16816(c, ah[0], ah[1], ah[2], ah[3], bl0, bl1);
                    MMA16816(c, al[0], al[1], al[2], al[3], bh0, bh1);
                }
            }
        }
        __syncthreads();
    }

    const int dir = n0 >> 11;
    const int nn0 = n0 & 2047;
    const float* bias = dir ? b_bw : b_fw;
    const int qr = lane >> 2;
    const int qc = (lane & 3) * 2;

#pragma unroll
    for (int mi = 0; mi < 2; mi++) {
#pragma unroll
        for (int ni = 0; ni < 4; ni++) {
            const float* c = acc[mi * 4 + ni];
            const int ncol = nw + ni * 8 + qc;
            const float bv0 = bias[nn0 + ncol];
            const float bv1 = bias[nn0 + ncol + 1];
#pragma unroll
            for (int half = 0; half < 2; half++) {
                const int m = m0 + mw + mi * 16 + qr + half * 8;
                const int t = m >> 6, b = m & 63;
                float* dst = dir
                    ? (g_xzb + ((size_t)(Tt - 1 - t) * Bb + b) * G4H + nn0 + ncol)
                    : (g_xzf + (size_t)m * G4H + nn0 + ncol);
                float2 o;
                o.x = c[half * 2 + 0] + bv0;
                o.y = c[half * 2 + 1] + bv1;
                *(float2*)dst = o;
            }
        }
    }
}

// =================================================================================
// init: reset barrier, seed h buf0 hi/lo from h0 ([b][H] layout = input layout)
// =================================================================================
__global__ void init_kernel(const float* __restrict__ h0_fw,
                            const float* __restrict__ h0_bw)
{
    int i = blockIdx.x * blockDim.x + threadIdx.x;
    if (i == 0) g_bar = 0u;
    if (i < BH) {
        float vf = h0_fw[i], vb = h0_bw[i];
        __nv_bfloat16 hf = __float2bfloat16(vf);
        __nv_bfloat16 hb = __float2bfloat16(vb);
        g_hh[i]      = hf;
        g_hl[i]      = __float2bfloat16(vf - __bfloat162float(hf));
        g_hh[BH + i] = hb;
        g_hl[BH + i] = __float2bfloat16(vb - __bfloat162float(hb));
    }
}

__device__ __forceinline__ float sigmoidf_fast(float x) {
    return __fdividef(1.f, 1.f + __expf(-x));
}

// =================================================================================
// Phase B: persistent bidirectional LSTM scan — tensor-core h@U (split-bf16).
// 128 CTAs: dir = blk>>6, jblk = blk&63 -> 8 hidden units -> 32 z-columns.
// 8 warps as 4 m-warps (16 batches) x 2 n-warps (16 cols), K=512 = 32 k16 steps.
// SMEM (bytes): h hi [64][520bf16] @0, h lo @66560, U hi [32][520] @133120,
//               U lo @166400, z fp32 [64][36] @199680, c fp32 [512] @208896.
// =================================================================================
#define HSTR 1040                       // smem row stride bytes (520 bf16)
#define OFF_HHI 0
#define OFF_HLO 66560
#define OFF_UHI 133120
#define OFF_ULO 166400
#define OFF_Z   199680
#define OFF_C   208896
#define SCAN_SMEM_BYTES 210944
#define ZST 36                          // z row stride (floats)

__global__ __launch_bounds__(256, 1) void lstm_scan(
    const float* __restrict__ U_fw, const float* __restrict__ U_bw,
    const float* __restrict__ c0_fw, const float* __restrict__ c0_bw,
    float* __restrict__ out, float* __restrict__ hT, float* __restrict__ cT)
{
    extern __shared__ __align__(16) char sml[];
    const uint32_t base = smem_u32(sml);
    __nv_bfloat16* uhi = (__nv_bfloat16*)(sml + OFF_UHI);
    __nv_bfloat16* ulo = (__nv_bfloat16*)(sml + OFF_ULO);
    float* z_s = (float*)(sml + OFF_Z);
    float* c_s = (float*)(sml + OFF_C);

    const int tid  = threadIdx.x;
    const int wid  = tid >> 5;
    const int lane = tid & 31;
    const int dir  = blockIdx.x >> 6;
    const int jblk = blockIdx.x & 63;
    const int j0   = jblk * 8;

    const float* __restrict__ U  = dir ? U_bw : U_fw;
    const float* __restrict__ c0 = dir ? c0_bw : c0_fw;
    const float* __restrict__ xz = dir ? g_xzb : g_xzf;

    // persistent U slice, split hi/lo, layout [c][k] (c = gate*8 + jj)
    for (int i = tid; i < 32 * 512; i += 256) {
        int c = i >> 9, k = i & 511;
        float v = U[(size_t)k * G4H + (c >> 3) * Hh + j0 + (c & 7)];
        __nv_bfloat16 hi = __float2bfloat16(v);
        uhi[c * 520 + k] = hi;
        ulo[c * 520 + k] = __float2bfloat16(v - __bfloat162float(hi));
    }
    for (int i = tid; i < 512; i += 256)
        c_s[i] = c0[(i >> 3) * Hh + j0 + (i & 7)];

    // warp tile: 4 m-warps x 2 n-warps
    const int mw = (wid >> 1) * 16;
    const int nw = (wid & 1) * 16;
    const uint32_t aHi = base + OFF_HHI + (uint32_t)((mw + (lane & 15)) * HSTR
                         + (lane >> 4) * 16);
    const uint32_t aLo = aHi + (OFF_HLO - OFF_HHI);
    const uint32_t bHi = base + OFF_UHI + (uint32_t)((nw + (lane & 7)
                         + ((lane >> 4) & 1) * 8) * HSTR + ((lane >> 3) & 1) * 16);
    const uint32_t bLo = bHi + (OFF_ULO - OFF_UHI);

    // gate-phase identities (2 outputs per thread)
    int gb[2], gj[2];
#pragma unroll
    for (int pp = 0; pp < 2; pp++) {
        int p = tid + pp * 256;
        gb[pp] = p >> 3;
        gj[pp] = p & 7;
    }
    const int qr = lane >> 2;
    const int qc = (lane & 3) * 2;

    for (int step = 0; step < Tt; step++) {
        const int rb = (step & 1) * 2 + dir;       // read buf index
        const int wb = ((step + 1) & 1) * 2 + dir; // write buf index

        // issue xz DRAM loads FIRST (latency overlaps h staging + MMA)
        float xzr[2][4];
#pragma unroll
        for (int pp = 0; pp < 2; pp++) {
            const float* row = xz + ((size_t)step * Bb + gb[pp]) * G4H + j0 + gj[pp];
#pragma unroll
            for (int gt = 0; gt < 4; gt++)
                xzr[pp][gt] = __ldcs(row + gt * Hh);
        }

        // stage h hi/lo from L2 into smem ([b][k], stride 520 bf16)
        {
            const uint4* srcH = (const uint4*)(g_hh + (size_t)rb * BH);
            const uint4* srcL = (const uint4*)(g_hl + (size_t)rb * BH);
#pragma unroll 4
            for (int i = tid; i < 4096; i += 256) {   // 4096 x 16B = 64KB per array
                uint4 vh = __ldcg(srcH + i);
                uint4 vl = __ldcg(srcL + i);
                uint32_t d = (uint32_t)((i >> 6) * HSTR + (i & 63) * 16);
                *(uint4*)(sml + OFF_HHI + d) = vh;
                *(uint4*)(sml + OFF_HLO + d) = vl;
            }
        }
        __syncthreads();

        // z = h @ U via mma.sync: 32 k16 steps, 3 split products
        float c0a[4] = {0.f, 0.f, 0.f, 0.f};
        float c1a[4] = {0.f, 0.f, 0.f, 0.f};
#pragma unroll 4
        for (int ks = 0; ks < 32; ks++) {
            const uint32_t kb = (uint32_t)ks * 32;
            uint32_t ah[4], al[4], bh[4], bl[4];
            LDSM4(ah[0], ah[1], ah[2], ah[3], aHi + kb);
            LDSM4(al[0], al[1], al[2], al[3], aLo + kb);
            LDSM4(bh[0], bh[1], bh[2], bh[3], bHi + kb);
            LDSM4(bl[0], bl[1], bl[2], bl[3], bLo + kb);
            MMA16816(c0a, ah[0], ah[1], ah[2], ah[3], bh[0], bh[1]);
            MMA16816(c1a, ah[0], ah[1], ah[2], ah[3], bh[2], bh[3]);
            MMA16816(c0a, ah[0], ah[1], ah[2], ah[3], bl[0], bl[1]);
            MMA16816(c1a, ah[0], ah[1], ah[2], ah[3], bl[2], bl[3]);
            MMA16816(c0a, al[0], al[1], al[2], al[3], bh[0], bh[1]);
            MMA16816(c1a, al[0], al[1], al[2], al[3], bh[2], bh[3]);
        }

        // publish z fragments to smem [b][c], stride ZST
        {
            const int r0 = mw + qr, r1 = r0 + 8;
            const int cb = nw + qc;
            *(float2*)&z_s[r0 * ZST + cb]     = make_float2(c0a[0], c0a[1]);
            *(float2*)&z_s[r1 * ZST + cb]     = make_float2(c0a[2], c0a[3]);
            *(float2*)&z_s[r0 * ZST + cb + 8] = make_float2(c1a[0], c1a[1]);
            *(float2*)&z_s[r1 * ZST + cb + 8] = make_float2(c1a[2], c1a[3]);
        }
        __syncthreads();

        // gates: 512 (b,jj) pairs, 2 per thread
#pragma unroll
        for (int pp = 0; pp < 2; pp++) {
            const int b = gb[pp], jj = gj[pp];
            const float* zrow = &z_s[b * ZST + jj];
            float zi = xzr[pp][0] + zrow[0];
            float zf = xzr[pp][1] + zrow[8];
            float zg = xzr[pp][2] + zrow[16];
            float zo = xzr[pp][3] + zrow[24];
            const int p = tid + pp * 256;
            float cold = c_s[p];
            float ig = sigmoidf_fast(zi);
            float fg = sigmoidf_fast(zf);
            float gg = tanhf(zg);
            float og = sigmoidf_fast(zo);
            float cn = fg * cold + ig * gg;
            float hn = og * tanhf(cn);
            c_s[p] = cn;
            const int j = j0 + jj;
            __nv_bfloat16 hi = __float2bfloat16(hn);
            g_hh[(size_t)wb * BH + b * Hh + j] = hi;
            g_hl[(size_t)wb * BH + b * Hh + j] =
                __float2bfloat16(hn - __bfloat162float(hi));
            int tout = dir ? (Tt - 1 - step) : step;
            out[((size_t)b * Tt + tout) * (2 * Hh) + dir * Hh + j] = hn;
            if (step == Tt - 1) {
                hT[b * 2 * Hh + dir * Hh + j] = hn;
                cT[b * 2 * Hh + dir * Hh + j] = cn;
            }
        }

        // grid barrier: fence, arrive (atomic), acquire-poll
        __threadfence();
        __syncthreads();
        if (tid == 0) {
            atomicAdd(&g_bar, 1u);
            unsigned target = (unsigned)(step + 1) * gridDim.x;
            unsigned v;
            do {
                asm volatile("ld.acquire.gpu.global.u32 %0, [%1];"
                             : "=r"(v) : "l"(&g_bar) : "memory");
                if (v >= target) break;
                __nanosleep(32);
            } while (true);
        }
        __syncthreads();
    }
}

// =================================================================================
extern "C" void kernel_launch(void* const* d_in, const int* in_sizes, int n_in,
                              void* d_out, int out_size)
{
    const int*   tokens = (const int*)  d_in[0];
    const float* h0_fw  = (const float*)d_in[1];
    const float* c0_fw  = (const float*)d_in[2];
    const float* h0_bw  = (const float*)d_in[3];
    const float* c0_bw  = (const float*)d_in[4];
    const float* emb    = (const float*)d_in[5];
    const float* W_fw   = (const float*)d_in[6];
    const float* U_fw   = (const float*)d_in[7];
    const float* b_fw   = (const float*)d_in[8];
    const float* W_bw   = (const float*)d_in[9];
    const float* U_bw   = (const float*)d_in[10];
    const float* b_bw   = (const float*)d_in[11];

    float* out = (float*)d_out;                       // [B,T,2H]
    float* hT  = out + (size_t)Bb * Tt * 2 * Hh;      // [B,2H]
    float* cT  = hT + (size_t)Bb * 2 * Hh;            // [B,2H]

    // prep: split inputs to bf16 hi/lo scratch
    {
        size_t na = (size_t)MK * KPAD;
        prep_A<<<(unsigned)((na + 255) / 256), 256>>>(tokens, emb);
        size_t nb = (size_t)4096 * KPAD;
        prep_B<<<(unsigned)((nb + 255) / 256), 256>>>(W_fw, W_bw);
    }
    init_kernel<<<128, 256>>>(h0_fw, h0_bw);

    // tensor-core input GEMM (mma.sync bf16 split)
    cudaFuncSetAttribute(gemm_hmma, cudaFuncAttributeMaxDynamicSharedMemorySize,
                         GEMM_SMEM);
    gemm_hmma<<<dim3(64, 256), 256, GEMM_SMEM>>>(b_fw, b_bw);

    // persistent LSTM scan (tensor-core h@U)
    cudaFuncSetAttribute(lstm_scan, cudaFuncAttributeMaxDynamicSharedMemorySize,
                         SCAN_SMEM_BYTES);
    lstm_scan<<<128, 256, SCAN_SMEM_BYTES>>>(U_fw, U_bw, c0_fw, c0_bw, out, hT, cT);
}

// round 9
// speedup vs baseline: 2.3027x; 1.0474x over previous
#include <cuda_runtime.h>
#include <cuda_bf16.h>
#include <math.h>
#include <stdint.h>

#define Vv 34004
#define Ee 300
#define Hh 512
#define Bb 64
#define Tt 512
#define G4H 2048
#define BH (Bb * Hh)
#define MK 32768          // M total = B*T
#define KPAD 320          // K padded to 320

// ---------------- scratch (device globals; no runtime allocation) ----------------
__device__ float g_xzf[67108864];          // [T][B][4H] fw pre-activations
__device__ float g_xzb[67108864];          // [T][B][4H] bw pre-activations (scan order)
__device__ __nv_bfloat16 g_hh[2 * 2 * BH]; // h hi split, ping-pong [buf][dir][b][H]
__device__ __nv_bfloat16 g_hl[2 * 2 * BH]; // h lo split
__device__ unsigned g_bar2[2];             // per-direction barrier counters
__device__ __nv_bfloat16 g_Ah[(size_t)MK * KPAD];   // emb-gathered A, hi split
__device__ __nv_bfloat16 g_Al[(size_t)MK * KPAD];   // lo split
__device__ __nv_bfloat16 g_Bh[(size_t)4096 * KPAD]; // W^T (B[n][k]), hi split (fw||bw)
__device__ __nv_bfloat16 g_Bl[(size_t)4096 * KPAD];

// ---------------- PTX helpers (sm_80-class: compile under compute_103) ----------
__device__ __forceinline__ uint32_t smem_u32(const void* p) {
    uint32_t a;
    asm("{ .reg .u64 t; cvta.to.shared.u64 t, %1; cvt.u32.u64 %0, t; }"
        : "=r"(a) : "l"(p));
    return a;
}
#define CP_ASYNC16(s, g) \
    asm volatile("cp.async.cg.shared.global [%0], [%1], 16;" :: "r"(s), "l"(g))
#define CP_COMMIT() asm volatile("cp.async.commit_group;" ::: "memory")
#define CP_WAIT1()  asm volatile("cp.async.wait_group 1;" ::: "memory")
#define CP_WAIT0()  asm volatile("cp.async.wait_group 0;" ::: "memory")

#define LDSM4(r0, r1, r2, r3, addr) \
    asm volatile("ldmatrix.sync.aligned.m8n8.x4.shared.b16 {%0,%1,%2,%3}, [%4];" \
                 : "=r"(r0), "=r"(r1), "=r"(r2), "=r"(r3) : "r"(addr))

#define MMA16816(c, a0, a1, a2, a3, b0, b1) \
    asm volatile("mma.sync.aligned.m16n8k16.row.col.f32.bf16.bf16.f32 " \
                 "{%0,%1,%2,%3},{%4,%5,%6,%7},{%8,%9},{%0,%1,%2,%3};" \
                 : "+f"((c)[0]), "+f"((c)[1]), "+f"((c)[2]), "+f"((c)[3]) \
                 : "r"(a0), "r"(a1), "r"(a2), "r"(a3), "r"(b0), "r"(b1))

// =================================================================================
// prep_A: gather emb rows, split fp32 -> bf16 hi/lo, pad K to 320
// =================================================================================
__global__ void prep_A(const int* __restrict__ tokens, const float* __restrict__ emb) {
    size_t idx = (size_t)blockIdx.x * blockDim.x + threadIdx.x;
    if (idx >= (size_t)MK * KPAD) return;
    int m = (int)(idx / KPAD), k = (int)(idx - (size_t)m * KPAD);
    int t = m >> 6, b = m & 63;
    int tok = tokens[b * Tt + t];
    float v = (k < Ee) ? emb[(size_t)tok * Ee + k] : 0.f;
    __nv_bfloat16 hi = __float2bfloat16(v);
    g_Ah[idx] = hi;
    g_Al[idx] = __float2bfloat16(v - __bfloat162float(hi));
}

// =================================================================================
// prep_B: B[n][k] = W[k][n] (fw n<2048, bw n>=2048), split hi/lo, pad K to 320
// =================================================================================
__global__ void prep_B(const float* __restrict__ W_fw, const float* __restrict__ W_bw) {
    size_t idx = (size_t)blockIdx.x * blockDim.x + threadIdx.x;
    if (idx >= (size_t)4096 * KPAD) return;
    int n = (int)(idx / KPAD), k = (int)(idx - (size_t)n * KPAD);
    int dir = n >> 11, nn = n & 2047;
    const float* W = dir ? W_bw : W_fw;
    float v = (k < Ee) ? W[(size_t)k * G4H + nn] : 0.f;
    __nv_bfloat16 hi = __float2bfloat16(v);
    g_Bh[idx] = hi;
    g_Bl[idx] = __float2bfloat16(v - __bfloat162float(hi));
}

// =================================================================================
// gemm_hmma: xz = A @ B^T + bias via mma.sync bf16 split (unchanged from R7/R8)
// =================================================================================
#define KC 64
#define SROW 144
#define SZ_A (128 * SROW)
#define SZ_B (64 * SROW)
#define BUFSZ (2 * SZ_A + 2 * SZ_B)
#define OFF_AH 0
#define OFF_AL SZ_A
#define OFF_BH (2 * SZ_A)
#define OFF_BL (2 * SZ_A + SZ_B)
#define GEMM_SMEM (2 * BUFSZ)

__global__ __launch_bounds__(256, 1) void gemm_hmma(
    const float* __restrict__ b_fw, const float* __restrict__ b_bw)
{
    extern __shared__ char smg[];
    const uint32_t base = smem_u32(smg);

    const int tid  = threadIdx.x;
    const int wid  = tid >> 5;
    const int lane = tid & 31;
    const int n0 = blockIdx.x * 64;
    const int m0 = blockIdx.y * 128;

    const int mw = (wid >> 1) * 32;
    const int nw = (wid & 1) * 32;

    const int la_row = tid >> 1;
    const int la_g0  = (tid & 1) * 4;
    const int lb_row = tid >> 2;
    const int lb_g0  = (tid & 3) * 2;

    auto load_chunk = [&](int ch, int buf) {
        const int k0 = ch * KC;
        const uint32_t bb = base + buf * BUFSZ;
        {
            const size_t gsrc = (size_t)(m0 + la_row) * KPAD + k0 + la_g0 * 8;
            const uint32_t sdst = bb + la_row * SROW + la_g0 * 16;
#pragma unroll
            for (int u = 0; u < 4; u++) {
                CP_ASYNC16(sdst + OFF_AH + u * 16, g_Ah + gsrc + u * 8);
                CP_ASYNC16(sdst + OFF_AL + u * 16, g_Al + gsrc + u * 8);
            }
        }
        {
            const size_t gsrc = (size_t)(n0 + lb_row) * KPAD + k0 + lb_g0 * 8;
            const uint32_t sdst = bb + lb_row * SROW + lb_g0 * 16;
#pragma unroll
            for (int u = 0; u < 2; u++) {
                CP_ASYNC16(sdst + OFF_BH + u * 16, g_Bh + gsrc + u * 8);
                CP_ASYNC16(sdst + OFF_BL + u * 16, g_Bl + gsrc + u * 8);
            }
        }
        CP_COMMIT();
    };

    float acc[8][4];
#pragma unroll
    for (int i = 0; i < 8; i++)
#pragma unroll
        for (int j = 0; j < 4; j++) acc[i][j] = 0.f;

    const uint32_t a_off = (uint32_t)((lane & 15) * SROW + (lane >> 4) * 16);
    const uint32_t b_off = (uint32_t)(((lane & 7) + ((lane >> 4) & 1) * 8) * SROW
                                      + ((lane >> 3) & 1) * 16);

    load_chunk(0, 0);

    const int NCH = KPAD / KC;
    for (int ch = 0; ch < NCH; ch++) {
        const int buf = ch & 1;
        if (ch + 1 < NCH) {
            load_chunk(ch + 1, (ch + 1) & 1);
            CP_WAIT1();
        } else {
            CP_WAIT0();
        }
        __syncthreads();

        const uint32_t bb = base + buf * BUFSZ;
        const uint32_t aH = bb + OFF_AH + mw * SROW + a_off;
        const uint32_t aL = bb + OFF_AL + mw * SROW + a_off;
        const uint32_t bH = bb + OFF_BH + nw * SROW + b_off;
        const uint32_t bL = bb + OFF_BL + nw * SROW + b_off;

#pragma unroll
        for (int ks = 0; ks < KC / 16; ks++) {
            const uint32_t kb = ks * 32;
            uint32_t ah0[4], ah1[4], al0[4], al1[4];
            LDSM4(ah0[0], ah0[1], ah0[2], ah0[3], aH + kb);
            LDSM4(ah1[0], ah1[1], ah1[2], ah1[3], aH + 16 * SROW + kb);
            LDSM4(al0[0], al0[1], al0[2], al0[3], aL + kb);
            LDSM4(al1[0], al1[1], al1[2], al1[3], aL + 16 * SROW + kb);
            uint32_t bh[8], bl[8];
            LDSM4(bh[0], bh[1], bh[2], bh[3], bH + kb);
            LDSM4(bh[4], bh[5], bh[6], bh[7], bH + 16 * SROW + kb);
            LDSM4(bl[0], bl[1], bl[2], bl[3], bL + kb);
            LDSM4(bl[4], bl[5], bl[6], bl[7], bL + 16 * SROW + kb);

#pragma unroll
            for (int mi = 0; mi < 2; mi++) {
                const uint32_t* ah = mi ? ah1 : ah0;
                const uint32_t* al = mi ? al1 : al0;
#pragma unroll
                for (int ni = 0; ni < 4; ni++) {
                    float* c = acc[mi * 4 + ni];
                    const uint32_t bh0 = bh[ni * 2], bh1 = bh[ni * 2 + 1];
                    const uint32_t bl0 = bl[ni * 2], bl1 = bl[ni * 2 + 1];
                    MMA16816(c, ah[0], ah[1], ah[2], ah[3], bh0, bh1);
                    MMA16816(c, ah[0], ah[1], ah[2], ah[3], bl0, bl1);
                    MMA16816(c, al[0], al[1], al[2], al[3], bh0, bh1);
                }
            }
        }
        __syncthreads();
    }

    const int dir = n0 >> 11;
    const int nn0 = n0 & 2047;
    const float* bias = dir ? b_bw : b_fw;
    const int qr = lane >> 2;
    const int qc = (lane & 3) * 2;

#pragma unroll
    for (int mi = 0; mi < 2; mi++) {
#pragma unroll
        for (int ni = 0; ni < 4; ni++) {
            const float* c = acc[mi * 4 + ni];
            const int ncol = nw + ni * 8 + qc;
            const float bv0 = bias[nn0 + ncol];
            const float bv1 = bias[nn0 + ncol + 1];
#pragma unroll
            for (int half = 0; half < 2; half++) {
                const int m = m0 + mw + mi * 16 + qr + half * 8;
                const int t = m >> 6, b = m & 63;
                float* dst = dir
                    ? (g_xzb + ((size_t)(Tt - 1 - t) * Bb + b) * G4H + nn0 + ncol)
                    : (g_xzf + (size_t)m * G4H + nn0 + ncol);
                float2 o;
                o.x = c[half * 2 + 0] + bv0;
                o.y = c[half * 2 + 1] + bv1;
                *(float2*)dst = o;
            }
        }
    }
}

// =================================================================================
// init: reset barriers, seed h buf0 hi/lo from h0 ([b][H] layout = input layout)
// =================================================================================
__global__ void init_kernel(const float* __restrict__ h0_fw,
                            const float* __restrict__ h0_bw)
{
    int i = blockIdx.x * blockDim.x + threadIdx.x;
    if (i < 2) g_bar2[i] = 0u;
    if (i < BH) {
        float vf = h0_fw[i], vb = h0_bw[i];
        __nv_bfloat16 hf = __float2bfloat16(vf);
        __nv_bfloat16 hb = __float2bfloat16(vb);
        g_hh[i]      = hf;
        g_hl[i]      = __float2bfloat16(vf - __bfloat162float(hf));
        g_hh[BH + i] = hb;
        g_hl[BH + i] = __float2bfloat16(vb - __bfloat162float(hb));
    }
}

__device__ __forceinline__ float sigmoidf_fast(float x) {
    return __fdividef(1.f, 1.f + __expf(-x));
}

// =================================================================================
// Phase B: persistent bidirectional LSTM scan — tensor-core h@U, K-split warps.
// 128 CTAs: dir = blk>>6, jblk = blk&63 -> 8 hidden units -> 32 z-columns.
// 8 warps = 4 m-warps (16 batches each) x 2 K-halves (256 each); every warp
// computes all 32 cols -> 4 accumulator fragments (better HMMA ILP).
// z partials [2][64][36] reduced in gate phase. cp.async h staging.
// Per-direction grid barrier (red.release + acquire-poll on 64 CTAs).
// =================================================================================
#define HSTR 1040                       // smem row stride bytes (520 bf16)
#define OFF_HHI 0
#define OFF_HLO 66560
#define OFF_UHI 133120
#define OFF_ULO 166400
#define OFF_Z   199680                  // [2][64][36] fp32 partials
#define OFF_C   218112
#define SCAN_SMEM_BYTES 220160
#define ZST 36

__global__ __launch_bounds__(256, 1) void lstm_scan(
    const float* __restrict__ U_fw, const float* __restrict__ U_bw,
    const float* __restrict__ c0_fw, const float* __restrict__ c0_bw,
    float* __restrict__ out, float* __restrict__ hT, float* __restrict__ cT)
{
    extern __shared__ __align__(16) char sml[];
    const uint32_t base = smem_u32(sml);
    __nv_bfloat16* uhi = (__nv_bfloat16*)(sml + OFF_UHI);
    __nv_bfloat16* ulo = (__nv_bfloat16*)(sml + OFF_ULO);
    float* z_s = (float*)(sml + OFF_Z);
    float* c_s = (float*)(sml + OFF_C);

    const int tid  = threadIdx.x;
    const int wid  = tid >> 5;
    const int lane = tid & 31;
    const int dir  = blockIdx.x >> 6;
    const int jblk = blockIdx.x & 63;
    const int j0   = jblk * 8;

    const float* __restrict__ U  = dir ? U_bw : U_fw;
    const float* __restrict__ c0 = dir ? c0_bw : c0_fw;
    const float* __restrict__ xz = dir ? g_xzb : g_xzf;

    // persistent U slice, split hi/lo, layout [c][k] (c = gate*8 + jj)
    for (int i = tid; i < 32 * 512; i += 256) {
        int c = i >> 9, k = i & 511;
        float v = U[(size_t)k * G4H + (c >> 3) * Hh + j0 + (c & 7)];
        __nv_bfloat16 hi = __float2bfloat16(v);
        uhi[c * 520 + k] = hi;
        ulo[c * 520 + k] = __float2bfloat16(v - __bfloat162float(hi));
    }
    for (int i = tid; i < 512; i += 256)
        c_s[i] = c0[(i >> 3) * Hh + j0 + (i & 7)];

    // warp roles: 4 m-warps x 2 K-halves; each warp does all 32 cols
    const int mwarp = wid & 3;
    const int khalf = wid >> 2;
    const uint32_t kofs = (uint32_t)khalf * 512;   // 256 bf16 = 512 bytes

    const uint32_t aHi = base + OFF_HHI
        + (uint32_t)((mwarp * 16 + (lane & 15)) * HSTR) + kofs + (lane >> 4) * 16;
    const uint32_t aLo = aHi + (OFF_HLO - OFF_HHI);
    const uint32_t rowB = (uint32_t)((lane & 7) + ((lane >> 4) & 1) * 8);
    const uint32_t bHi0 = base + OFF_UHI + rowB * HSTR + kofs + ((lane >> 3) & 1) * 16;
    const uint32_t bHi1 = bHi0 + 16 * HSTR;
    const uint32_t bLo0 = bHi0 + (OFF_ULO - OFF_UHI);
    const uint32_t bLo1 = bHi1 + (OFF_ULO - OFF_UHI);

    // gate-phase identities (2 outputs per thread)
    int gb[2], gj[2];
#pragma unroll
    for (int pp = 0; pp < 2; pp++) {
        int p = tid + pp * 256;
        gb[pp] = p >> 3;
        gj[pp] = p & 7;
    }
    const int qr = lane >> 2;
    const int qc = (lane & 3) * 2;

    // prefetch xz for step 0
    float xzr[2][4];
#pragma unroll
    for (int pp = 0; pp < 2; pp++) {
        const float* row = xz + (size_t)gb[pp] * G4H + j0 + gj[pp];
#pragma unroll
        for (int gt = 0; gt < 4; gt++)
            xzr[pp][gt] = __ldcs(row + gt * Hh);
    }

    for (int step = 0; step < Tt; step++) {
        const int rb = (step & 1) * 2 + dir;       // read buf index
        const int wb = ((step + 1) & 1) * 2 + dir; // write buf index

        // stage h hi/lo from L2 via cp.async ([b][k], stride 520 bf16)
        {
            const __nv_bfloat16* srcH = g_hh + (size_t)rb * BH;
            const __nv_bfloat16* srcL = g_hl + (size_t)rb * BH;
#pragma unroll 4
            for (int i = tid; i < 4096; i += 256) {   // 4096 x 16B per array
                uint32_t d = (uint32_t)((i >> 6) * HSTR + (i & 63) * 16);
                CP_ASYNC16(base + OFF_HHI + d, srcH + i * 8);
                CP_ASYNC16(base + OFF_HLO + d, srcL + i * 8);
            }
            CP_COMMIT();
            CP_WAIT0();
        }
        __syncthreads();

        // z_partial = h[mrows, khalf] @ U[khalf, 32 cols]: 16 k16 steps,
        // 6 LDSM + 12 HMMA per step, 4 independent accumulator chains
        float acc[4][4];
#pragma unroll
        for (int i = 0; i < 4; i++)
#pragma unroll
            for (int j = 0; j < 4; j++) acc[i][j] = 0.f;

#pragma unroll 4
        for (int ks = 0; ks < 16; ks++) {
            const uint32_t kb = (uint32_t)ks * 32;
            uint32_t ah[4], al[4], bh0[4], bh1[4], bl0[4], bl1[4];
            LDSM4(ah[0], ah[1], ah[2], ah[3], aHi + kb);
            LDSM4(al[0], al[1], al[2], al[3], aLo + kb);
            LDSM4(bh0[0], bh0[1], bh0[2], bh0[3], bHi0 + kb);
            LDSM4(bh1[0], bh1[1], bh1[2], bh1[3], bHi1 + kb);
            LDSM4(bl0[0], bl0[1], bl0[2], bl0[3], bLo0 + kb);
            LDSM4(bl1[0], bl1[1], bl1[2], bl1[3], bLo1 + kb);

            MMA16816(acc[0], ah[0], ah[1], ah[2], ah[3], bh0[0], bh0[1]);
            MMA16816(acc[1], ah[0], ah[1], ah[2], ah[3], bh0[2], bh0[3]);
            MMA16816(acc[2], ah[0], ah[1], ah[2], ah[3], bh1[0], bh1[1]);
            MMA16816(acc[3], ah[0], ah[1], ah[2], ah[3], bh1[2], bh1[3]);

            MMA16816(acc[0], ah[0], ah[1], ah[2], ah[3], bl0[0], bl0[1]);
            MMA16816(acc[1], ah[0], ah[1], ah[2], ah[3], bl0[2], bl0[3]);
            MMA16816(acc[2], ah[0], ah[1], ah[2], ah[3], bl1[0], bl1[1]);
            MMA16816(acc[3], ah[0], ah[1], ah[2], ah[3], bl1[2], bl1[3]);

            MMA16816(acc[0], al[0], al[1], al[2], al[3], bh0[0], bh0[1]);
            MMA16816(acc[1], al[0], al[1], al[2], al[3], bh0[2], bh0[3]);
            MMA16816(acc[2], al[0], al[1], al[2], al[3], bh1[0], bh1[1]);
            MMA16816(acc[3], al[0], al[1], al[2], al[3], bh1[2], bh1[3]);
        }

        // publish z partials: z_s[khalf][row][col]
        {
            float* zh = z_s + khalf * 2304;
            const int r0 = mwarp * 16 + qr, r1 = r0 + 8;
#pragma unroll
            for (int i = 0; i < 4; i++) {
                const int cb = i * 8 + qc;
                *(float2*)&zh[r0 * ZST + cb] = make_float2(acc[i][0], acc[i][1]);
                *(float2*)&zh[r1 * ZST + cb] = make_float2(acc[i][2], acc[i][3]);
            }
        }
        __syncthreads();

        // gates: 512 (b,jj) pairs, 2 per thread; reduce the 2 K-half partials
#pragma unroll
        for (int pp = 0; pp < 2; pp++) {
            const int b = gb[pp], jj = gj[pp];
            const float* z1 = z_s + b * ZST + jj;
            const float* z2 = z1 + 2304;
            float zi = xzr[pp][0] + z1[0]  + z2[0];
            float zf = xzr[pp][1] + z1[8]  + z2[8];
            float zg = xzr[pp][2] + z1[16] + z2[16];
            float zo = xzr[pp][3] + z1[24] + z2[24];
            const int p = tid + pp * 256;
            float cold = c_s[p];
            float ig = sigmoidf_fast(zi);
            float fg = sigmoidf_fast(zf);
            float gg = tanhf(zg);
            float og = sigmoidf_fast(zo);
            float cn = fg * cold + ig * gg;
            float hn = og * tanhf(cn);
            c_s[p] = cn;
            const int j = j0 + jj;
            __nv_bfloat16 hi = __float2bfloat16(hn);
            g_hh[(size_t)wb * BH + b * Hh + j] = hi;
            g_hl[(size_t)wb * BH + b * Hh + j] =
                __float2bfloat16(hn - __bfloat162float(hi));
            int tout = dir ? (Tt - 1 - step) : step;
            out[((size_t)b * Tt + tout) * (2 * Hh) + dir * Hh + j] = hn;
            if (step == Tt - 1) {
                hT[b * 2 * Hh + dir * Hh + j] = hn;
                cT[b * 2 * Hh + dir * Hh + j] = cn;
            }
        }

        // prefetch next step's xz (DRAM latency hides behind barrier wait)
        if (step + 1 < Tt) {
#pragma unroll
            for (int pp = 0; pp < 2; pp++) {
                const float* row = xz + ((size_t)(step + 1) * Bb + gb[pp]) * G4H
                                   + j0 + gj[pp];
#pragma unroll
                for (int gt = 0; gt < 4; gt++)
                    xzr[pp][gt] = __ldcs(row + gt * Hh);
            }
        }

        // per-direction grid barrier: release-arrive + acquire-poll on 64 CTAs
        __syncthreads();
        if (tid == 0) {
            asm volatile("red.release.gpu.global.add.u32 [%0], 1;"
                         :: "l"(&g_bar2[dir]) : "memory");
            unsigned target = (unsigned)(step + 1) * 64u;
            unsigned v;
            do {
                asm volatile("ld.acquire.gpu.global.u32 %0, [%1];"
                             : "=r"(v) : "l"(&g_bar2[dir]) : "memory");
                if (v >= target) break;
                __nanosleep(32);
            } while (true);
        }
        __syncthreads();
    }
}

// =================================================================================
extern "C" void kernel_launch(void* const* d_in, const int* in_sizes, int n_in,
                              void* d_out, int out_size)
{
    const int*   tokens = (const int*)  d_in[0];
    const float* h0_fw  = (const float*)d_in[1];
    const float* c0_fw  = (const float*)d_in[2];
    const float* h0_bw  = (const float*)d_in[3];
    const float* c0_bw  = (const float*)d_in[4];
    const float* emb    = (const float*)d_in[5];
    const float* W_fw   = (const float*)d_in[6];
    const float* U_fw   = (const float*)d_in[7];
    const float* b_fw   = (const float*)d_in[8];
    const float* W_bw   = (const float*)d_in[9];
    const float* U_bw   = (const float*)d_in[10];
    const float* b_bw   = (const float*)d_in[11];

    float* out = (float*)d_out;                       // [B,T,2H]
    float* hT  = out + (size_t)Bb * Tt * 2 * Hh;      // [B,2H]
    float* cT  = hT + (size_t)Bb * 2 * Hh;            // [B,2H]

    // prep: split inputs to bf16 hi/lo scratch
    {
        size_t na = (size_t)MK * KPAD;
        prep_A<<<(unsigned)((na + 255) / 256), 256>>>(tokens, emb);
        size_t nb = (size_t)4096 * KPAD;
        prep_B<<<(unsigned)((nb + 255) / 256), 256>>>(W_fw, W_bw);
    }
    init_kernel<<<128, 256>>>(h0_fw, h0_bw);

    // tensor-core input GEMM (mma.sync bf16 split)
    cudaFuncSetAttribute(gemm_hmma, cudaFuncAttributeMaxDynamicSharedMemorySize,
                         GEMM_SMEM);
    gemm_hmma<<<dim3(64, 256), 256, GEMM_SMEM>>>(b_fw, b_bw);

    // persistent LSTM scan (tensor-core h@U, K-split warps)
    cudaFuncSetAttribute(lstm_scan, cudaFuncAttributeMaxDynamicSharedMemorySize,
                         SCAN_SMEM_BYTES);
    lstm_scan<<<128, 256, SCAN_SMEM_BYTES>>>(U_fw, U_bw, c0_fw, c0_bw, out, hT, cT);
}